// round 13
// baseline (speedup 1.0000x reference)
#include <cuda_runtime.h>
#include <cuda_bf16.h>
#include <mma.h>
#include <math.h>
#include <stdint.h>

using namespace nvcuda;

#define B_      256
#define T_      256
#define D_      512
#define UNITS_  1024
#define NCL_    512
#define FOURU_  4096

// ---------------- static device scratch (no allocs allowed) ----------------
__device__ float g_Zx[(size_t)T_ * B_ * FOURU_];     // [t][b][j'] = x_t @ Wx (permuted), NO bias
__device__ float g_Wwperm[(size_t)NCL_ * FOURU_];
__device__ float g_bperm[FOURU_];
__device__ __nv_bfloat16 g_Us[3][(size_t)FOURU_ * UNITS_];   // U splits, [n=j'][k] (K-major)
__device__ __nv_bfloat16 g_Wxs[3][(size_t)FOURU_ * D_];      // Wx splits, [n=j'][k] (K-major)
__device__ __nv_bfloat16 g_xs[3][(size_t)B_ * T_ * D_];      // x splits, [m=b*T+t][k]
__device__ __nv_bfloat16 g_hs[2][3][B_ * UNITS_];            // h splits ping-pong [b][k]
__device__ float g_h0[B_ * UNITS_];
__device__ float g_h1[B_ * UNITS_];
__device__ float g_c[B_ * UNITS_];
__device__ int   g_idx[B_];
__device__ float g_lpart[(size_t)8 * B_ * NCL_];     // logit partials

// ---------------- numerics helpers (bit-matching XLA) ----------------
__device__ __forceinline__ float hsig(float z) {
    float t = __fadd_rn(__fmul_rn(0.2f, z), 0.5f);
    return fminf(fmaxf(t, 0.0f), 1.0f);
}
__device__ __forceinline__ float tanh_xla(float x) {
    float ax = fabsf(x);
    if (ax < 0.0004f) return x;
    float xc = fminf(fmaxf(x, -9.0f), 9.0f);
    float x2 = __fmul_rn(xc, xc);
    float p = -2.76076847742355e-16f;
    p = fmaf(p, x2, 2.00018790482477e-13f);
    p = fmaf(p, x2, -8.60467152213735e-11f);
    p = fmaf(p, x2, 5.12229709037114e-08f);
    p = fmaf(p, x2, 1.48572235717979e-05f);
    p = fmaf(p, x2, 6.37261928875436e-04f);
    p = fmaf(p, x2, 4.89352455891786e-03f);
    float num = __fmul_rn(xc, p);
    float q = 1.19825839466702e-06f;
    q = fmaf(q, x2, 1.18534705686654e-04f);
    q = fmaf(q, x2, 2.26843463243900e-03f);
    q = fmaf(q, x2, 4.89352518554385e-03f);
    return __fdiv_rn(num, q);
}

__device__ __forceinline__ uint32_t smem_u32(const void* p) {
    uint32_t a;
    asm("{ .reg .u64 t; cvta.to.shared.u64 t, %1; cvt.u32.u64 %0, t; }" : "=r"(a) : "l"(p));
    return a;
}
__device__ __forceinline__ void cp_async16(uint32_t dst, const void* src) {
    asm volatile("cp.async.cg.shared.global [%0], [%1], 16;" :: "r"(dst), "l"(src));
}
__device__ __forceinline__ void cp_commit() {
    asm volatile("cp.async.commit_group;");
}
__device__ __forceinline__ void cp_wait1() {
    asm volatile("cp.async.wait_group 1;");
}
__device__ __forceinline__ void cp_wait0() {
    asm volatile("cp.async.wait_group 0;");
}

// ---------------- init ----------------
__global__ void init_kernel() {
    int stride = gridDim.x * blockDim.x;
    for (int i = blockIdx.x * blockDim.x + threadIdx.x; i < B_ * UNITS_; i += stride) {
        g_h0[i] = 0.0f;
        g_c[i] = 0.0f;
        g_hs[0][0][i] = __float2bfloat16(0.0f);
        g_hs[0][1][i] = __float2bfloat16(0.0f);
        g_hs[0][2][i] = __float2bfloat16(0.0f);
        if (i < B_) g_idx[i] = -1;
    }
}

// ---------------- permute weights + build all bf16 splits ----------------
__global__ void permute_kernel(const float* __restrict__ W,
                               const float* __restrict__ U,
                               const float* __restrict__ b,
                               const float* __restrict__ x) {
    int stride = gridDim.x * blockDim.x;
    int tid0 = blockIdx.x * blockDim.x + threadIdx.x;
    // Ww / bias, gate-interleaved columns j' = 4u + g
    for (int i = tid0; i < NCL_ * FOURU_; i += stride) {
        int k  = i >> 12;
        int jp = i & 4095;
        int src = ((jp & 3) << 10) + (jp >> 2);
        g_Wwperm[i] = W[((size_t)(k + D_) << 12) + src];
        if (k == 0) g_bperm[jp] = b[src];
    }
    // U transposed to [n=j'][k], split into 3 bf16 terms
    for (int i = tid0; i < FOURU_ * UNITS_; i += stride) {
        int jp = i >> 10;
        int k  = i & 1023;
        int src = ((jp & 3) << 10) + (jp >> 2);
        float v = U[((size_t)k << 12) + src];
        __nv_bfloat16 v1 = __float2bfloat16(v);
        float r1 = v - __bfloat162float(v1);
        __nv_bfloat16 v2 = __float2bfloat16(r1);
        float r2 = r1 - __bfloat162float(v2);
        g_Us[0][i] = v1;
        g_Us[1][i] = v2;
        g_Us[2][i] = __float2bfloat16(r2);
    }
    // Wx transposed to [n=j'][k], split into 3 bf16 terms
    for (int i = tid0; i < FOURU_ * D_; i += stride) {
        int jp = i >> 9;
        int k  = i & 511;
        int src = ((jp & 3) << 10) + (jp >> 2);
        float v = W[((size_t)k << 12) + src];
        __nv_bfloat16 v1 = __float2bfloat16(v);
        float r1 = v - __bfloat162float(v1);
        __nv_bfloat16 v2 = __float2bfloat16(r1);
        float r2 = r1 - __bfloat162float(v2);
        g_Wxs[0][i] = v1;
        g_Wxs[1][i] = v2;
        g_Wxs[2][i] = __float2bfloat16(r2);
    }
    // x split into 3 bf16 terms, [m][k] row-major (natural layout)
    for (size_t i = tid0; i < (size_t)B_ * T_ * D_; i += stride) {
        float v = x[i];
        __nv_bfloat16 v1 = __float2bfloat16(v);
        float r1 = v - __bfloat162float(v1);
        __nv_bfloat16 v2 = __float2bfloat16(r1);
        float r2 = r1 - __bfloat162float(v2);
        g_xs[0][i] = v1;
        g_xs[1][i] = v2;
        g_xs[2][i] = __float2bfloat16(r2);
    }
}

// ---------------- shared wmma GEMM config ----------------
// CTA tile M=64 x N=64, 8 warps as 2(m) x 4(n), warp tile 32x16.
// K in 32-wide stages (two k16 sub-steps), cp.async double buffered.
// accA holds only the a1*b1 pair; accS the 5 small pairs (drop 2^-24 pairs);
// merged with one __fadd_rn per element.
#define SKT     32
#define APAD    40
#define A_PLANE (64 * APAD)            // 2560 bf16
#define B_PLANE (64 * APAD)
#define ABUF    (3 * A_PLANE)
#define BBUF    (3 * B_PLANE)
#define BUFELEM (ABUF + BBUF)          // 15360 bf16 = 30720 B
#define SMEM_STEP (2 * BUFELEM * 2)    // 61440 B
#define STG_LD  68

// small-term pairs (exclude (0,0) -> accA; drop (1,2),(2,1) ~2^-24)
__device__ __constant__ int c_si[5] = {0, 1, 1, 0, 2};
__device__ __constant__ int c_sj[5] = {1, 0, 1, 2, 0};

// ---------------- precompute: Zx = x @ Wxperm via wmma split-6 ----------------
__global__ void __launch_bounds__(256, 2) precompute_mma_kernel() {
    extern __shared__ char smem[];
    __nv_bfloat16* sb = (__nv_bfloat16*)smem;
    uint32_t sb_addr = smem_u32(smem);

    int tid = threadIdx.x;
    int wid = tid >> 5;
    int wm = wid & 1;
    int wn = wid >> 1;
    int n0 = blockIdx.x * 64;
    int m0 = blockIdx.y * 64;

    wmma::fragment<wmma::accumulator, 16, 16, 16, float> accA[2], accS[2];
#pragma unroll
    for (int i = 0; i < 2; i++) {
        wmma::fill_fragment(accA[i], 0.0f);
        wmma::fill_fragment(accS[i], 0.0f);
    }

    auto load_tile = [&](int kt, int buf) {
        uint32_t base = sb_addr + (uint32_t)buf * (BUFELEM * 2);
#pragma unroll
        for (int i = 0; i < 6; i++) {
            int idx = i * 256 + tid;
            if (idx < 768) {
                int s = idx >> 8;
                int rem = idx & 255;
                int row = rem >> 2, kc = rem & 3;
                uint32_t dst = base + (uint32_t)(s * A_PLANE + row * APAD + kc * 8) * 2;
                const void* src = &g_xs[s][(size_t)(m0 + row) * D_ + kt * SKT + kc * 8];
                cp_async16(dst, src);
            } else {
                int bidx = idx - 768;
                int s = bidx >> 8;
                int rem = bidx & 255;
                int n = rem >> 2, kc = rem & 3;
                uint32_t dst = base + (uint32_t)(ABUF + s * B_PLANE + n * APAD + kc * 8) * 2;
                const void* src = &g_Wxs[s][(size_t)(n0 + n) * D_ + kt * SKT + kc * 8];
                cp_async16(dst, src);
            }
        }
    };

    load_tile(0, 0);
    cp_commit();

    for (int kt = 0; kt < D_ / SKT; kt++) {
        int buf = kt & 1;
        if (kt + 1 < D_ / SKT) {
            load_tile(kt + 1, buf ^ 1);
            cp_commit();
            cp_wait1();
        } else {
            cp_wait0();
        }
        __syncthreads();

        const __nv_bfloat16* abase = sb + (size_t)buf * BUFELEM;
        const __nv_bfloat16* bbase = abase + ABUF;

#pragma unroll
        for (int ksub = 0; ksub < 2; ksub++) {
            wmma::fragment<wmma::matrix_a, 16, 16, 16, __nv_bfloat16, wmma::row_major> af[3][2];
            wmma::fragment<wmma::matrix_b, 16, 16, 16, __nv_bfloat16, wmma::col_major> bf[3];
#pragma unroll
            for (int s = 0; s < 3; s++) {
#pragma unroll
                for (int im = 0; im < 2; im++)
                    wmma::load_matrix_sync(af[s][im],
                        abase + s * A_PLANE + (wm * 32 + im * 16) * APAD + ksub * 16, APAD);
                wmma::load_matrix_sync(bf[s],
                    bbase + s * B_PLANE + (wn * 16) * APAD + ksub * 16, APAD);
            }
#pragma unroll
            for (int im = 0; im < 2; im++)
                wmma::mma_sync(accA[im], af[0][im], bf[0], accA[im]);
#pragma unroll
            for (int p = 0; p < 5; p++)
#pragma unroll
                for (int im = 0; im < 2; im++)
                    wmma::mma_sync(accS[im], af[c_si[p]][im], bf[c_sj[p]], accS[im]);
        }
        __syncthreads();
    }

#pragma unroll
    for (int im = 0; im < 2; im++)
#pragma unroll
        for (int e = 0; e < accA[im].num_elements; e++)
            accA[im].x[e] = __fadd_rn(accA[im].x[e], accS[im].x[e]);

    float* stage = (float*)smem;
#pragma unroll
    for (int im = 0; im < 2; im++)
        wmma::store_matrix_sync(
            stage + (wm * 32 + im * 16) * STG_LD + wn * 16,
            accA[im], STG_LD, wmma::mem_row_major);
    __syncthreads();

#pragma unroll
    for (int it = 0; it < 4; it++) {
        int id = it * 256 + tid;
        int rrow = id >> 4;
        int qc = id & 15;
        int m = m0 + rrow;             // m = b*T + t
        int b = m >> 8;
        int t = m & 255;
        float4 v = *(const float4*)&stage[rrow * STG_LD + qc * 4];
        *(float4*)&g_Zx[((size_t)t * B_ + b) * FOURU_ + n0 + qc * 4] = v;
    }
}

// ---------------- step: wmma bf16 split-6 GEMM + fused gates epilogue ----------------
__global__ void __launch_bounds__(256, 2) step_mma_kernel(int t) {
    extern __shared__ char smem[];
    __nv_bfloat16* sb = (__nv_bfloat16*)smem;
    uint32_t sb_addr = smem_u32(smem);

    int tid = threadIdx.x;
    int wid = tid >> 5;
    int wm = wid & 1;
    int wn = wid >> 1;
    int n0 = blockIdx.x * 64;
    int m0 = blockIdx.y * 64;
    const __nv_bfloat16* hsrc = &g_hs[t & 1][0][0];
    const size_t HPLANE = (size_t)B_ * UNITS_;

    wmma::fragment<wmma::accumulator, 16, 16, 16, float> accA[2], accS[2];
#pragma unroll
    for (int i = 0; i < 2; i++) {
        wmma::fill_fragment(accA[i], 0.0f);
        wmma::fill_fragment(accS[i], 0.0f);
    }

    auto load_tile = [&](int kt, int buf) {
        uint32_t base = sb_addr + (uint32_t)buf * (BUFELEM * 2);
#pragma unroll
        for (int i = 0; i < 6; i++) {
            int idx = i * 256 + tid;
            if (idx < 768) {
                int s = idx >> 8;
                int rem = idx & 255;
                int row = rem >> 2, kc = rem & 3;
                uint32_t dst = base + (uint32_t)(s * A_PLANE + row * APAD + kc * 8) * 2;
                const void* src = hsrc + (size_t)s * HPLANE +
                                  (size_t)(m0 + row) * UNITS_ + kt * SKT + kc * 8;
                cp_async16(dst, src);
            } else {
                int bidx = idx - 768;
                int s = bidx >> 8;
                int rem = bidx & 255;
                int n = rem >> 2, kc = rem & 3;
                uint32_t dst = base + (uint32_t)(ABUF + s * B_PLANE + n * APAD + kc * 8) * 2;
                const void* src = &g_Us[s][(size_t)(n0 + n) * UNITS_ + kt * SKT + kc * 8];
                cp_async16(dst, src);
            }
        }
    };

    load_tile(0, 0);
    cp_commit();

    for (int kt = 0; kt < UNITS_ / SKT; kt++) {
        int buf = kt & 1;
        if (kt + 1 < UNITS_ / SKT) {
            load_tile(kt + 1, buf ^ 1);
            cp_commit();
            cp_wait1();
        } else {
            cp_wait0();
        }
        __syncthreads();

        const __nv_bfloat16* abase = sb + (size_t)buf * BUFELEM;
        const __nv_bfloat16* bbase = abase + ABUF;

#pragma unroll
        for (int ksub = 0; ksub < 2; ksub++) {
            wmma::fragment<wmma::matrix_a, 16, 16, 16, __nv_bfloat16, wmma::row_major> af[3][2];
            wmma::fragment<wmma::matrix_b, 16, 16, 16, __nv_bfloat16, wmma::col_major> bf[3];
#pragma unroll
            for (int s = 0; s < 3; s++) {
#pragma unroll
                for (int im = 0; im < 2; im++)
                    wmma::load_matrix_sync(af[s][im],
                        abase + s * A_PLANE + (wm * 32 + im * 16) * APAD + ksub * 16, APAD);
                wmma::load_matrix_sync(bf[s],
                    bbase + s * B_PLANE + (wn * 16) * APAD + ksub * 16, APAD);
            }
            // main term -> accA (bit-identical chain to R11/R12)
#pragma unroll
            for (int im = 0; im < 2; im++)
                wmma::mma_sync(accA[im], af[0][im], bf[0], accA[im]);
            // 5 small terms -> accS
#pragma unroll
            for (int p = 0; p < 5; p++)
#pragma unroll
                for (int im = 0; im < 2; im++)
                    wmma::mma_sync(accS[im], af[c_si[p]][im], bf[c_sj[p]], accS[im]);
        }
        __syncthreads();
    }

#pragma unroll
    for (int im = 0; im < 2; im++)
#pragma unroll
        for (int e = 0; e < accA[im].num_elements; e++)
            accA[im].x[e] = __fadd_rn(accA[im].x[e], accS[im].x[e]);

    float* stage = (float*)smem;
#pragma unroll
    for (int im = 0; im < 2; im++)
        wmma::store_matrix_sync(
            stage + (wm * 32 + im * 16) * STG_LD + wn * 16,
            accA[im], STG_LD, wmma::mem_row_major);
    __syncthreads();

    float* h_out = (t & 1) ? g_h0 : g_h1;
    int pnew = (t + 1) & 1;
#pragma unroll
    for (int it = 0; it < 4; it++) {
        int id = it * 256 + tid;
        int rrow = id >> 4;
        int qc = id & 15;
        int bat = m0 + rrow;
        int idx = g_idx[bat];
        int jb = n0 + qc * 4;

        float4 zx4 = *(const float4*)&g_Zx[((size_t)t * B_ + bat) * FOURU_ + jb];
        float ins[4] = {zx4.x, zx4.y, zx4.z, zx4.w};
        if (idx >= 0) {
            float4 ww = *(const float4*)&g_Wwperm[(size_t)idx * FOURU_ + jb];
            ins[0] = __fadd_rn(ins[0], ww.x);
            ins[1] = __fadd_rn(ins[1], ww.y);
            ins[2] = __fadd_rn(ins[2], ww.z);
            ins[3] = __fadd_rn(ins[3], ww.w);
        }
        float4 b4 = *(const float4*)&g_bperm[jb];
        float bv[4] = {b4.x, b4.y, b4.z, b4.w};
        float4 ac4 = *(const float4*)&stage[rrow * STG_LD + qc * 4];
        float av[4] = {ac4.x, ac4.y, ac4.z, ac4.w};
        float z[4];
#pragma unroll
        for (int g = 0; g < 4; g++)
            z[g] = __fadd_rn(__fadd_rn(ins[g], av[g]), bv[g]);

        int u = jb >> 2;
        float cold = g_c[bat * UNITS_ + u];
        float m1 = __fmul_rn(hsig(z[1]), cold);
        float m2 = __fmul_rn(hsig(z[0]), tanh_xla(z[2]));
        float cn = __fadd_rn(m1, m2);
        float hn = __fmul_rn(hsig(z[3]), tanh_xla(cn));
        g_c[bat * UNITS_ + u] = cn;
        h_out[bat * UNITS_ + u] = hn;

        __nv_bfloat16 h1 = __float2bfloat16(hn);
        float r1 = hn - __bfloat162float(h1);
        __nv_bfloat16 h2 = __float2bfloat16(r1);
        float r2 = r1 - __bfloat162float(h2);
        __nv_bfloat16 h3 = __float2bfloat16(r2);
        g_hs[pnew][0][bat * UNITS_ + u] = h1;
        g_hs[pnew][1][bat * UNITS_ + u] = h2;
        g_hs[pnew][2][bat * UNITS_ + u] = h3;
    }
}

// ---------------- logits partials: h_new @ Wout, 64x64 tiles, K split x8 ----------------
#define BK 16
#define LBM 64
#define LBN 64
#define LASTRIDE (LBM + 4)

__global__ void __launch_bounds__(256) logits_kernel(const float* __restrict__ Wout, int t) {
    const float* __restrict__ h = (t & 1) ? g_h0 : g_h1;   // h_new written by step t

    __shared__ float As[BK][LASTRIDE];
    __shared__ float Bs[BK][LBN];
    int tid = threadIdx.x;
    int tx = tid & 15, ty = tid >> 4;
    int m0 = blockIdx.y * LBM;
    int n0 = blockIdx.x * LBN;
    int kc = blockIdx.z;
    int kbeg = kc * 128;

    float acc[4][4];
#pragma unroll
    for (int i = 0; i < 4; i++)
#pragma unroll
        for (int j = 0; j < 4; j++) acc[i][j] = 0.0f;

    for (int k0 = kbeg; k0 < kbeg + 128; k0 += BK) {
        {
            int row = tid >> 2, c4 = tid & 3;
            float4 v = *(const float4*)&h[(size_t)(m0 + row) * UNITS_ + k0 + c4 * 4];
            As[c4 * 4 + 0][row] = v.x;
            As[c4 * 4 + 1][row] = v.y;
            As[c4 * 4 + 2][row] = v.z;
            As[c4 * 4 + 3][row] = v.w;
        }
        {
            int row = tid >> 4, c4 = tid & 15;
            *(float4*)&Bs[row][c4 * 4] =
                *(const float4*)&Wout[(size_t)(k0 + row) * NCL_ + n0 + c4 * 4];
        }
        __syncthreads();
#pragma unroll
        for (int kk = 0; kk < BK; kk++) {
            float4 a4 = *(const float4*)&As[kk][ty * 4];
            float4 b4 = *(const float4*)&Bs[kk][tx * 4];
            float a[4] = {a4.x, a4.y, a4.z, a4.w};
            float bb[4] = {b4.x, b4.y, b4.z, b4.w};
#pragma unroll
            for (int i = 0; i < 4; i++)
#pragma unroll
                for (int j = 0; j < 4; j++) acc[i][j] = fmaf(a[i], bb[j], acc[i][j]);
        }
        __syncthreads();
    }

#pragma unroll
    for (int i = 0; i < 4; i++) {
        int m = m0 + ty * 4 + i;
        float* dst = &g_lpart[((size_t)kc * B_ + m) * NCL_ + n0 + tx * 4];
        *(float4*)dst = make_float4(acc[i][0], acc[i][1], acc[i][2], acc[i][3]);
    }
}

// ---------------- reduce partials + bias, argmax (tie -> lowest index) ----------------
__global__ void __launch_bounds__(256) argmax_kernel(const float* __restrict__ bout,
                                                     float* __restrict__ out, int t) {
    int b = blockIdx.x;
    int tid = threadIdx.x;
    unsigned long long best = 0ull;
    for (int n = tid; n < NCL_; n += 256) {
        float l = 0.0f;
#pragma unroll
        for (int kc = 0; kc < 8; kc++)
            l = __fadd_rn(l, g_lpart[((size_t)kc * B_ + b) * NCL_ + n]);
        l = __fadd_rn(l, bout[n]);
        unsigned u = __float_as_uint(l);
        u = (u & 0x80000000u) ? ~u : (u | 0x80000000u);
        unsigned long long key = ((unsigned long long)u << 32) | (unsigned)(NCL_ - 1 - n);
        best = best > key ? best : key;
    }
    __shared__ unsigned long long red[256];
    red[tid] = best;
    __syncthreads();
    for (int s = 128; s > 0; s >>= 1) {
        if (tid < s) red[tid] = red[tid] > red[tid + s] ? red[tid] : red[tid + s];
        __syncthreads();
    }
    if (tid == 0) {
        int idx = (NCL_ - 1) - (int)(red[0] & 0xffffffffu);
        g_idx[b] = idx;
        out[(size_t)b * T_ + t] = (float)idx;   // output dtype: float32
    }
}

// ---------------- launch (3 + 256*3 = 771 graph nodes, proven infra-safe) ----------------
extern "C" void kernel_launch(void* const* d_in, const int* in_sizes, int n_in,
                              void* d_out, int out_size) {
    (void)out_size;
    const float *x = 0, *W = 0, *U = 0, *b = 0, *Wout = 0, *bout = 0;
    const float* big[2] = {0, 0};
    int nbig = 0;
    for (int i = 0; i < n_in; i++) {
        switch (in_sizes[i]) {
            case 33554432: x    = (const float*)d_in[i]; break;  // 256*256*512
            case 524288:   Wout = (const float*)d_in[i]; break;  // 1024*512
            case 4096:     b    = (const float*)d_in[i]; break;
            case 512:      bout = (const float*)d_in[i]; break;
            case 4194304:  if (nbig < 2) big[nbig++] = (const float*)d_in[i]; break;
            default: break;
        }
    }
    W = big[0];
    U = big[1];
    float* out = (float*)d_out;

    cudaFuncSetAttribute(step_mma_kernel, cudaFuncAttributeMaxDynamicSharedMemorySize, SMEM_STEP);
    cudaFuncSetAttribute(precompute_mma_kernel, cudaFuncAttributeMaxDynamicSharedMemorySize, SMEM_STEP);

    init_kernel<<<512, 256>>>();
    permute_kernel<<<2048, 256>>>(W, U, b, x);
    precompute_mma_kernel<<<dim3(FOURU_ / 64, (B_ * T_) / 64), 256, SMEM_STEP>>>();

    for (int t = 0; t < T_; t++) {
        step_mma_kernel<<<dim3(FOURU_ / 64, B_ / 64), 256, SMEM_STEP>>>(t);
        logits_kernel<<<dim3(NCL_ / LBN, B_ / LBM, 8), 256>>>(Wout, t);
        argmax_kernel<<<B_, 256>>>(bout, out, t);
    }
}

// round 14
// speedup vs baseline: 2.0816x; 2.0816x over previous
#include <cuda_runtime.h>
#include <cuda_bf16.h>
#include <mma.h>
#include <math.h>
#include <stdint.h>

using namespace nvcuda;

#define B_      256
#define T_      256
#define D_      512
#define UNITS_  1024
#define NCL_    512
#define FOURU_  4096

// ---------------- static device scratch (no allocs allowed) ----------------
__device__ float g_Zx[(size_t)T_ * B_ * FOURU_];     // [t][b][j'] = x_t @ Wx (permuted), NO bias
__device__ float g_Wwperm[(size_t)NCL_ * FOURU_];
__device__ float g_bperm[FOURU_];
__device__ __nv_bfloat16 g_Us[3][(size_t)FOURU_ * UNITS_];   // U splits, [n=j'][k] (K-major)
__device__ __nv_bfloat16 g_Wxs[3][(size_t)FOURU_ * D_];      // Wx splits, [n=j'][k] (K-major)
__device__ __nv_bfloat16 g_xs[3][(size_t)B_ * T_ * D_];      // x splits, [m=b*T+t][k]
__device__ __nv_bfloat16 g_hs[2][3][B_ * UNITS_];            // h splits ping-pong [b][k]
__device__ float g_h0[B_ * UNITS_];
__device__ float g_h1[B_ * UNITS_];
__device__ float g_c[B_ * UNITS_];
__device__ int   g_idx[B_];
__device__ float g_lpart[(size_t)8 * B_ * NCL_];     // logit partials

// ---------------- numerics helpers (bit-matching XLA) ----------------
__device__ __forceinline__ float hsig(float z) {
    float t = __fadd_rn(__fmul_rn(0.2f, z), 0.5f);
    return fminf(fmaxf(t, 0.0f), 1.0f);
}
__device__ __forceinline__ float tanh_xla(float x) {
    float ax = fabsf(x);
    if (ax < 0.0004f) return x;
    float xc = fminf(fmaxf(x, -9.0f), 9.0f);
    float x2 = __fmul_rn(xc, xc);
    float p = -2.76076847742355e-16f;
    p = fmaf(p, x2, 2.00018790482477e-13f);
    p = fmaf(p, x2, -8.60467152213735e-11f);
    p = fmaf(p, x2, 5.12229709037114e-08f);
    p = fmaf(p, x2, 1.48572235717979e-05f);
    p = fmaf(p, x2, 6.37261928875436e-04f);
    p = fmaf(p, x2, 4.89352455891786e-03f);
    float num = __fmul_rn(xc, p);
    float q = 1.19825839466702e-06f;
    q = fmaf(q, x2, 1.18534705686654e-04f);
    q = fmaf(q, x2, 2.26843463243900e-03f);
    q = fmaf(q, x2, 4.89352518554385e-03f);
    return __fdiv_rn(num, q);
}

__device__ __forceinline__ uint32_t smem_u32(const void* p) {
    uint32_t a;
    asm("{ .reg .u64 t; cvta.to.shared.u64 t, %1; cvt.u32.u64 %0, t; }" : "=r"(a) : "l"(p));
    return a;
}
__device__ __forceinline__ void cp_async16(uint32_t dst, const void* src) {
    asm volatile("cp.async.cg.shared.global [%0], [%1], 16;" :: "r"(dst), "l"(src));
}
__device__ __forceinline__ void cp_commit() {
    asm volatile("cp.async.commit_group;");
}
__device__ __forceinline__ void cp_wait1() {
    asm volatile("cp.async.wait_group 1;");
}
__device__ __forceinline__ void cp_wait0() {
    asm volatile("cp.async.wait_group 0;");
}

// ---------------- init ----------------
__global__ void init_kernel() {
    int stride = gridDim.x * blockDim.x;
    for (int i = blockIdx.x * blockDim.x + threadIdx.x; i < B_ * UNITS_; i += stride) {
        g_h0[i] = 0.0f;
        g_c[i] = 0.0f;
        g_hs[0][0][i] = __float2bfloat16(0.0f);
        g_hs[0][1][i] = __float2bfloat16(0.0f);
        g_hs[0][2][i] = __float2bfloat16(0.0f);
        if (i < B_) g_idx[i] = -1;
    }
}

// ---------------- permute weights + build all bf16 splits ----------------
__global__ void permute_kernel(const float* __restrict__ W,
                               const float* __restrict__ U,
                               const float* __restrict__ b,
                               const float* __restrict__ x) {
    int stride = gridDim.x * blockDim.x;
    int tid0 = blockIdx.x * blockDim.x + threadIdx.x;
    // Ww / bias, gate-interleaved columns j' = 4u + g
    for (int i = tid0; i < NCL_ * FOURU_; i += stride) {
        int k  = i >> 12;
        int jp = i & 4095;
        int src = ((jp & 3) << 10) + (jp >> 2);
        g_Wwperm[i] = W[((size_t)(k + D_) << 12) + src];
        if (k == 0) g_bperm[jp] = b[src];
    }
    // U transposed to [n=j'][k], split into 3 bf16 terms
    for (int i = tid0; i < FOURU_ * UNITS_; i += stride) {
        int jp = i >> 10;
        int k  = i & 1023;
        int src = ((jp & 3) << 10) + (jp >> 2);
        float v = U[((size_t)k << 12) + src];
        __nv_bfloat16 v1 = __float2bfloat16(v);
        float r1 = v - __bfloat162float(v1);
        __nv_bfloat16 v2 = __float2bfloat16(r1);
        float r2 = r1 - __bfloat162float(v2);
        g_Us[0][i] = v1;
        g_Us[1][i] = v2;
        g_Us[2][i] = __float2bfloat16(r2);
    }
    // Wx transposed to [n=j'][k], split into 3 bf16 terms
    for (int i = tid0; i < FOURU_ * D_; i += stride) {
        int jp = i >> 9;
        int k  = i & 511;
        int src = ((jp & 3) << 10) + (jp >> 2);
        float v = W[((size_t)k << 12) + src];
        __nv_bfloat16 v1 = __float2bfloat16(v);
        float r1 = v - __bfloat162float(v1);
        __nv_bfloat16 v2 = __float2bfloat16(r1);
        float r2 = r1 - __bfloat162float(v2);
        g_Wxs[0][i] = v1;
        g_Wxs[1][i] = v2;
        g_Wxs[2][i] = __float2bfloat16(r2);
    }
    // x split into 3 bf16 terms, [m][k] row-major (natural layout)
    for (size_t i = tid0; i < (size_t)B_ * T_ * D_; i += stride) {
        float v = x[i];
        __nv_bfloat16 v1 = __float2bfloat16(v);
        float r1 = v - __bfloat162float(v1);
        __nv_bfloat16 v2 = __float2bfloat16(r1);
        float r2 = r1 - __bfloat162float(v2);
        g_xs[0][i] = v1;
        g_xs[1][i] = v2;
        g_xs[2][i] = __float2bfloat16(r2);
    }
}

// ---------------- shared wmma GEMM config ----------------
// CTA tile M=64 x N=64, 8 warps as 2(m) x 4(n), warp tile 32x16.
// K in 32-wide stages (two k16 sub-steps), cp.async double buffered.
// accA holds only the a1*b1 pair; accS the 5 small pairs (2^-24 pairs dropped);
// merged with one __fadd_rn per element.
// NOTE: pair-index tables MUST be local const arrays (compile-time foldable).
// R13 used __constant__ arrays -> dynamic fragment indexing -> local-memory
// spills (regs 128, L1 56%, 2x slowdown). Do not repeat.
#define SKT     32
#define APAD    40
#define A_PLANE (64 * APAD)            // 2560 bf16
#define B_PLANE (64 * APAD)
#define ABUF    (3 * A_PLANE)
#define BBUF    (3 * B_PLANE)
#define BUFELEM (ABUF + BBUF)          // 15360 bf16 = 30720 B
#define SMEM_STEP (2 * BUFELEM * 2)    // 61440 B
#define STG_LD  68

// ---------------- precompute: Zx = x @ Wxperm via wmma split-6 ----------------
__global__ void __launch_bounds__(256, 2) precompute_mma_kernel() {
    extern __shared__ char smem[];
    __nv_bfloat16* sb = (__nv_bfloat16*)smem;
    uint32_t sb_addr = smem_u32(smem);

    int tid = threadIdx.x;
    int wid = tid >> 5;
    int wm = wid & 1;
    int wn = wid >> 1;
    int n0 = blockIdx.x * 64;
    int m0 = blockIdx.y * 64;

    wmma::fragment<wmma::accumulator, 16, 16, 16, float> accA[2], accS[2];
#pragma unroll
    for (int i = 0; i < 2; i++) {
        wmma::fill_fragment(accA[i], 0.0f);
        wmma::fill_fragment(accS[i], 0.0f);
    }

    auto load_tile = [&](int kt, int buf) {
        uint32_t base = sb_addr + (uint32_t)buf * (BUFELEM * 2);
#pragma unroll
        for (int i = 0; i < 6; i++) {
            int idx = i * 256 + tid;
            if (idx < 768) {
                int s = idx >> 8;
                int rem = idx & 255;
                int row = rem >> 2, kc = rem & 3;
                uint32_t dst = base + (uint32_t)(s * A_PLANE + row * APAD + kc * 8) * 2;
                const void* src = &g_xs[s][(size_t)(m0 + row) * D_ + kt * SKT + kc * 8];
                cp_async16(dst, src);
            } else {
                int bidx = idx - 768;
                int s = bidx >> 8;
                int rem = bidx & 255;
                int n = rem >> 2, kc = rem & 3;
                uint32_t dst = base + (uint32_t)(ABUF + s * B_PLANE + n * APAD + kc * 8) * 2;
                const void* src = &g_Wxs[s][(size_t)(n0 + n) * D_ + kt * SKT + kc * 8];
                cp_async16(dst, src);
            }
        }
    };

    // local const tables: compile-time foldable, fragments stay in registers
    const int si[5] = {0, 1, 1, 0, 2};
    const int sj[5] = {1, 0, 1, 2, 0};

    load_tile(0, 0);
    cp_commit();

    for (int kt = 0; kt < D_ / SKT; kt++) {
        int buf = kt & 1;
        if (kt + 1 < D_ / SKT) {
            load_tile(kt + 1, buf ^ 1);
            cp_commit();
            cp_wait1();
        } else {
            cp_wait0();
        }
        __syncthreads();

        const __nv_bfloat16* abase = sb + (size_t)buf * BUFELEM;
        const __nv_bfloat16* bbase = abase + ABUF;

#pragma unroll
        for (int ksub = 0; ksub < 2; ksub++) {
            wmma::fragment<wmma::matrix_a, 16, 16, 16, __nv_bfloat16, wmma::row_major> af[3][2];
            wmma::fragment<wmma::matrix_b, 16, 16, 16, __nv_bfloat16, wmma::col_major> bf[3];
#pragma unroll
            for (int s = 0; s < 3; s++) {
#pragma unroll
                for (int im = 0; im < 2; im++)
                    wmma::load_matrix_sync(af[s][im],
                        abase + s * A_PLANE + (wm * 32 + im * 16) * APAD + ksub * 16, APAD);
                wmma::load_matrix_sync(bf[s],
                    bbase + s * B_PLANE + (wn * 16) * APAD + ksub * 16, APAD);
            }
#pragma unroll
            for (int im = 0; im < 2; im++)
                wmma::mma_sync(accA[im], af[0][im], bf[0], accA[im]);
#pragma unroll
            for (int p = 0; p < 5; p++)
#pragma unroll
                for (int im = 0; im < 2; im++)
                    wmma::mma_sync(accS[im], af[si[p]][im], bf[sj[p]], accS[im]);
        }
        __syncthreads();
    }

#pragma unroll
    for (int im = 0; im < 2; im++)
#pragma unroll
        for (int e = 0; e < accA[im].num_elements; e++)
            accA[im].x[e] = __fadd_rn(accA[im].x[e], accS[im].x[e]);

    float* stage = (float*)smem;
#pragma unroll
    for (int im = 0; im < 2; im++)
        wmma::store_matrix_sync(
            stage + (wm * 32 + im * 16) * STG_LD + wn * 16,
            accA[im], STG_LD, wmma::mem_row_major);
    __syncthreads();

#pragma unroll
    for (int it = 0; it < 4; it++) {
        int id = it * 256 + tid;
        int rrow = id >> 4;
        int qc = id & 15;
        int m = m0 + rrow;             // m = b*T + t
        int b = m >> 8;
        int t = m & 255;
        float4 v = *(const float4*)&stage[rrow * STG_LD + qc * 4];
        *(float4*)&g_Zx[((size_t)t * B_ + b) * FOURU_ + n0 + qc * 4] = v;
    }
}

// ---------------- step: wmma bf16 split-6 GEMM + fused gates epilogue ----------------
__global__ void __launch_bounds__(256, 2) step_mma_kernel(int t) {
    extern __shared__ char smem[];
    __nv_bfloat16* sb = (__nv_bfloat16*)smem;
    uint32_t sb_addr = smem_u32(smem);

    int tid = threadIdx.x;
    int wid = tid >> 5;
    int wm = wid & 1;
    int wn = wid >> 1;
    int n0 = blockIdx.x * 64;
    int m0 = blockIdx.y * 64;
    const __nv_bfloat16* hsrc = &g_hs[t & 1][0][0];
    const size_t HPLANE = (size_t)B_ * UNITS_;

    wmma::fragment<wmma::accumulator, 16, 16, 16, float> accA[2], accS[2];
#pragma unroll
    for (int i = 0; i < 2; i++) {
        wmma::fill_fragment(accA[i], 0.0f);
        wmma::fill_fragment(accS[i], 0.0f);
    }

    auto load_tile = [&](int kt, int buf) {
        uint32_t base = sb_addr + (uint32_t)buf * (BUFELEM * 2);
#pragma unroll
        for (int i = 0; i < 6; i++) {
            int idx = i * 256 + tid;
            if (idx < 768) {
                int s = idx >> 8;
                int rem = idx & 255;
                int row = rem >> 2, kc = rem & 3;
                uint32_t dst = base + (uint32_t)(s * A_PLANE + row * APAD + kc * 8) * 2;
                const void* src = hsrc + (size_t)s * HPLANE +
                                  (size_t)(m0 + row) * UNITS_ + kt * SKT + kc * 8;
                cp_async16(dst, src);
            } else {
                int bidx = idx - 768;
                int s = bidx >> 8;
                int rem = bidx & 255;
                int n = rem >> 2, kc = rem & 3;
                uint32_t dst = base + (uint32_t)(ABUF + s * B_PLANE + n * APAD + kc * 8) * 2;
                const void* src = &g_Us[s][(size_t)(n0 + n) * UNITS_ + kt * SKT + kc * 8];
                cp_async16(dst, src);
            }
        }
    };

    // local const tables: compile-time foldable, fragments stay in registers
    const int si[5] = {0, 1, 1, 0, 2};
    const int sj[5] = {1, 0, 1, 2, 0};

    load_tile(0, 0);
    cp_commit();

    for (int kt = 0; kt < UNITS_ / SKT; kt++) {
        int buf = kt & 1;
        if (kt + 1 < UNITS_ / SKT) {
            load_tile(kt + 1, buf ^ 1);
            cp_commit();
            cp_wait1();
        } else {
            cp_wait0();
        }
        __syncthreads();

        const __nv_bfloat16* abase = sb + (size_t)buf * BUFELEM;
        const __nv_bfloat16* bbase = abase + ABUF;

#pragma unroll
        for (int ksub = 0; ksub < 2; ksub++) {
            wmma::fragment<wmma::matrix_a, 16, 16, 16, __nv_bfloat16, wmma::row_major> af[3][2];
            wmma::fragment<wmma::matrix_b, 16, 16, 16, __nv_bfloat16, wmma::col_major> bf[3];
#pragma unroll
            for (int s = 0; s < 3; s++) {
#pragma unroll
                for (int im = 0; im < 2; im++)
                    wmma::load_matrix_sync(af[s][im],
                        abase + s * A_PLANE + (wm * 32 + im * 16) * APAD + ksub * 16, APAD);
                wmma::load_matrix_sync(bf[s],
                    bbase + s * B_PLANE + (wn * 16) * APAD + ksub * 16, APAD);
            }
            // main term -> accA (bit-identical chain to R11/R12)
#pragma unroll
            for (int im = 0; im < 2; im++)
                wmma::mma_sync(accA[im], af[0][im], bf[0], accA[im]);
            // 5 small terms -> accS
#pragma unroll
            for (int p = 0; p < 5; p++)
#pragma unroll
                for (int im = 0; im < 2; im++)
                    wmma::mma_sync(accS[im], af[si[p]][im], bf[sj[p]], accS[im]);
        }
        __syncthreads();
    }

#pragma unroll
    for (int im = 0; im < 2; im++)
#pragma unroll
        for (int e = 0; e < accA[im].num_elements; e++)
            accA[im].x[e] = __fadd_rn(accA[im].x[e], accS[im].x[e]);

    float* stage = (float*)smem;
#pragma unroll
    for (int im = 0; im < 2; im++)
        wmma::store_matrix_sync(
            stage + (wm * 32 + im * 16) * STG_LD + wn * 16,
            accA[im], STG_LD, wmma::mem_row_major);
    __syncthreads();

    float* h_out = (t & 1) ? g_h0 : g_h1;
    int pnew = (t + 1) & 1;
#pragma unroll
    for (int it = 0; it < 4; it++) {
        int id = it * 256 + tid;
        int rrow = id >> 4;
        int qc = id & 15;
        int bat = m0 + rrow;
        int idx = g_idx[bat];
        int jb = n0 + qc * 4;

        float4 zx4 = *(const float4*)&g_Zx[((size_t)t * B_ + bat) * FOURU_ + jb];
        float ins[4] = {zx4.x, zx4.y, zx4.z, zx4.w};
        if (idx >= 0) {
            float4 ww = *(const float4*)&g_Wwperm[(size_t)idx * FOURU_ + jb];
            ins[0] = __fadd_rn(ins[0], ww.x);
            ins[1] = __fadd_rn(ins[1], ww.y);
            ins[2] = __fadd_rn(ins[2], ww.z);
            ins[3] = __fadd_rn(ins[3], ww.w);
        }
        float4 b4 = *(const float4*)&g_bperm[jb];
        float bv[4] = {b4.x, b4.y, b4.z, b4.w};
        float4 ac4 = *(const float4*)&stage[rrow * STG_LD + qc * 4];
        float av[4] = {ac4.x, ac4.y, ac4.z, ac4.w};
        float z[4];
#pragma unroll
        for (int g = 0; g < 4; g++)
            z[g] = __fadd_rn(__fadd_rn(ins[g], av[g]), bv[g]);

        int u = jb >> 2;
        float cold = g_c[bat * UNITS_ + u];
        float m1 = __fmul_rn(hsig(z[1]), cold);
        float m2 = __fmul_rn(hsig(z[0]), tanh_xla(z[2]));
        float cn = __fadd_rn(m1, m2);
        float hn = __fmul_rn(hsig(z[3]), tanh_xla(cn));
        g_c[bat * UNITS_ + u] = cn;
        h_out[bat * UNITS_ + u] = hn;

        __nv_bfloat16 h1 = __float2bfloat16(hn);
        float r1 = hn - __bfloat162float(h1);
        __nv_bfloat16 h2 = __float2bfloat16(r1);
        float r2 = r1 - __bfloat162float(h2);
        __nv_bfloat16 h3 = __float2bfloat16(r2);
        g_hs[pnew][0][bat * UNITS_ + u] = h1;
        g_hs[pnew][1][bat * UNITS_ + u] = h2;
        g_hs[pnew][2][bat * UNITS_ + u] = h3;
    }
}

// ---------------- logits partials: h_new @ Wout, 64x64 tiles, K split x8 ----------------
#define BK 16
#define LBM 64
#define LBN 64
#define LASTRIDE (LBM + 4)

__global__ void __launch_bounds__(256) logits_kernel(const float* __restrict__ Wout, int t) {
    const float* __restrict__ h = (t & 1) ? g_h0 : g_h1;   // h_new written by step t

    __shared__ float As[BK][LASTRIDE];
    __shared__ float Bs[BK][LBN];
    int tid = threadIdx.x;
    int tx = tid & 15, ty = tid >> 4;
    int m0 = blockIdx.y * LBM;
    int n0 = blockIdx.x * LBN;
    int kc = blockIdx.z;
    int kbeg = kc * 128;

    float acc[4][4];
#pragma unroll
    for (int i = 0; i < 4; i++)
#pragma unroll
        for (int j = 0; j < 4; j++) acc[i][j] = 0.0f;

    for (int k0 = kbeg; k0 < kbeg + 128; k0 += BK) {
        {
            int row = tid >> 2, c4 = tid & 3;
            float4 v = *(const float4*)&h[(size_t)(m0 + row) * UNITS_ + k0 + c4 * 4];
            As[c4 * 4 + 0][row] = v.x;
            As[c4 * 4 + 1][row] = v.y;
            As[c4 * 4 + 2][row] = v.z;
            As[c4 * 4 + 3][row] = v.w;
        }
        {
            int row = tid >> 4, c4 = tid & 15;
            *(float4*)&Bs[row][c4 * 4] =
                *(const float4*)&Wout[(size_t)(k0 + row) * NCL_ + n0 + c4 * 4];
        }
        __syncthreads();
#pragma unroll
        for (int kk = 0; kk < BK; kk++) {
            float4 a4 = *(const float4*)&As[kk][ty * 4];
            float4 b4 = *(const float4*)&Bs[kk][tx * 4];
            float a[4] = {a4.x, a4.y, a4.z, a4.w};
            float bb[4] = {b4.x, b4.y, b4.z, b4.w};
#pragma unroll
            for (int i = 0; i < 4; i++)
#pragma unroll
                for (int j = 0; j < 4; j++) acc[i][j] = fmaf(a[i], bb[j], acc[i][j]);
        }
        __syncthreads();
    }

#pragma unroll
    for (int i = 0; i < 4; i++) {
        int m = m0 + ty * 4 + i;
        float* dst = &g_lpart[((size_t)kc * B_ + m) * NCL_ + n0 + tx * 4];
        *(float4*)dst = make_float4(acc[i][0], acc[i][1], acc[i][2], acc[i][3]);
    }
}

// ---------------- reduce partials + bias, argmax (tie -> lowest index) ----------------
__global__ void __launch_bounds__(256) argmax_kernel(const float* __restrict__ bout,
                                                     float* __restrict__ out, int t) {
    int b = blockIdx.x;
    int tid = threadIdx.x;
    unsigned long long best = 0ull;
    for (int n = tid; n < NCL_; n += 256) {
        float l = 0.0f;
#pragma unroll
        for (int kc = 0; kc < 8; kc++)
            l = __fadd_rn(l, g_lpart[((size_t)kc * B_ + b) * NCL_ + n]);
        l = __fadd_rn(l, bout[n]);
        unsigned u = __float_as_uint(l);
        u = (u & 0x80000000u) ? ~u : (u | 0x80000000u);
        unsigned long long key = ((unsigned long long)u << 32) | (unsigned)(NCL_ - 1 - n);
        best = best > key ? best : key;
    }
    __shared__ unsigned long long red[256];
    red[tid] = best;
    __syncthreads();
    for (int s = 128; s > 0; s >>= 1) {
        if (tid < s) red[tid] = red[tid] > red[tid + s] ? red[tid] : red[tid + s];
        __syncthreads();
    }
    if (tid == 0) {
        int idx = (NCL_ - 1) - (int)(red[0] & 0xffffffffu);
        g_idx[b] = idx;
        out[(size_t)b * T_ + t] = (float)idx;   // output dtype: float32
    }
}

// ---------------- launch (3 + 256*3 = 771 graph nodes, proven infra-safe) ----------------
extern "C" void kernel_launch(void* const* d_in, const int* in_sizes, int n_in,
                              void* d_out, int out_size) {
    (void)out_size;
    const float *x = 0, *W = 0, *U = 0, *b = 0, *Wout = 0, *bout = 0;
    const float* big[2] = {0, 0};
    int nbig = 0;
    for (int i = 0; i < n_in; i++) {
        switch (in_sizes[i]) {
            case 33554432: x    = (const float*)d_in[i]; break;  // 256*256*512
            case 524288:   Wout = (const float*)d_in[i]; break;  // 1024*512
            case 4096:     b    = (const float*)d_in[i]; break;
            case 512:      bout = (const float*)d_in[i]; break;
            case 4194304:  if (nbig < 2) big[nbig++] = (const float*)d_in[i]; break;
            default: break;
        }
    }
    W = big[0];
    U = big[1];
    float* out = (float*)d_out;

    cudaFuncSetAttribute(step_mma_kernel, cudaFuncAttributeMaxDynamicSharedMemorySize, SMEM_STEP);
    cudaFuncSetAttribute(precompute_mma_kernel, cudaFuncAttributeMaxDynamicSharedMemorySize, SMEM_STEP);

    init_kernel<<<512, 256>>>();
    permute_kernel<<<2048, 256>>>(W, U, b, x);
    precompute_mma_kernel<<<dim3(FOURU_ / 64, (B_ * T_) / 64), 256, SMEM_STEP>>>();

    for (int t = 0; t < T_; t++) {
        step_mma_kernel<<<dim3(FOURU_ / 64, B_ / 64), 256, SMEM_STEP>>>(t);
        logits_kernel<<<dim3(NCL_ / LBN, B_ / LBM, 8), 256>>>(Wout, t);
        argmax_kernel<<<B_, 256>>>(bout, out, t);
    }
}

// round 15
// speedup vs baseline: 2.1335x; 1.0249x over previous
#include <cuda_runtime.h>
#include <cuda_bf16.h>
#include <mma.h>
#include <math.h>
#include <stdint.h>

using namespace nvcuda;

#define B_      256
#define T_      256
#define D_      512
#define UNITS_  1024
#define NCL_    512
#define FOURU_  4096

// ---------------- static device scratch (no allocs allowed) ----------------
__device__ float g_Zx[(size_t)T_ * B_ * FOURU_];     // [t][b][j'] = x_t @ Wx (permuted), NO bias
__device__ float g_Wwperm[(size_t)NCL_ * FOURU_];
__device__ float g_bperm[FOURU_];
__device__ __nv_bfloat16 g_Us[3][(size_t)FOURU_ * UNITS_];   // U splits, [n=j'][k] (K-major)
__device__ __nv_bfloat16 g_Wxs[3][(size_t)FOURU_ * D_];      // Wx splits, [n=j'][k] (K-major)
__device__ __nv_bfloat16 g_xs[3][(size_t)B_ * T_ * D_];      // x splits, [m=b*T+t][k]
__device__ __nv_bfloat16 g_hs[2][3][B_ * UNITS_];            // h splits ping-pong [b][k]
__device__ float g_h0[B_ * UNITS_];
__device__ float g_h1[B_ * UNITS_];
__device__ float g_c[B_ * UNITS_];
__device__ int   g_idx[B_];
__device__ float g_lpart[(size_t)8 * B_ * NCL_];     // logit partials

// ---------------- numerics helpers (bit-matching XLA) ----------------
__device__ __forceinline__ float hsig(float z) {
    float t = __fadd_rn(__fmul_rn(0.2f, z), 0.5f);
    return fminf(fmaxf(t, 0.0f), 1.0f);
}
__device__ __forceinline__ float tanh_xla(float x) {
    float ax = fabsf(x);
    if (ax < 0.0004f) return x;
    float xc = fminf(fmaxf(x, -9.0f), 9.0f);
    float x2 = __fmul_rn(xc, xc);
    float p = -2.76076847742355e-16f;
    p = fmaf(p, x2, 2.00018790482477e-13f);
    p = fmaf(p, x2, -8.60467152213735e-11f);
    p = fmaf(p, x2, 5.12229709037114e-08f);
    p = fmaf(p, x2, 1.48572235717979e-05f);
    p = fmaf(p, x2, 6.37261928875436e-04f);
    p = fmaf(p, x2, 4.89352455891786e-03f);
    float num = __fmul_rn(xc, p);
    float q = 1.19825839466702e-06f;
    q = fmaf(q, x2, 1.18534705686654e-04f);
    q = fmaf(q, x2, 2.26843463243900e-03f);
    q = fmaf(q, x2, 4.89352518554385e-03f);
    return __fdiv_rn(num, q);
}

__device__ __forceinline__ uint32_t smem_u32(const void* p) {
    uint32_t a;
    asm("{ .reg .u64 t; cvta.to.shared.u64 t, %1; cvt.u32.u64 %0, t; }" : "=r"(a) : "l"(p));
    return a;
}
__device__ __forceinline__ void cp_async16(uint32_t dst, const void* src) {
    asm volatile("cp.async.cg.shared.global [%0], [%1], 16;" :: "r"(dst), "l"(src));
}
__device__ __forceinline__ void cp_commit() {
    asm volatile("cp.async.commit_group;");
}
__device__ __forceinline__ void cp_wait1() {
    asm volatile("cp.async.wait_group 1;");
}
__device__ __forceinline__ void cp_wait0() {
    asm volatile("cp.async.wait_group 0;");
}

// ---------------- init ----------------
__global__ void init_kernel() {
    int stride = gridDim.x * blockDim.x;
    for (int i = blockIdx.x * blockDim.x + threadIdx.x; i < B_ * UNITS_; i += stride) {
        g_h0[i] = 0.0f;
        g_c[i] = 0.0f;
        g_hs[0][0][i] = __float2bfloat16(0.0f);
        g_hs[0][1][i] = __float2bfloat16(0.0f);
        g_hs[0][2][i] = __float2bfloat16(0.0f);
        if (i < B_) g_idx[i] = -1;
    }
}

// ---------------- permute weights + build all bf16 splits ----------------
__global__ void permute_kernel(const float* __restrict__ W,
                               const float* __restrict__ U,
                               const float* __restrict__ b,
                               const float* __restrict__ x) {
    int stride = gridDim.x * blockDim.x;
    int tid0 = blockIdx.x * blockDim.x + threadIdx.x;
    // Ww / bias, gate-interleaved columns j' = 4u + g
    for (int i = tid0; i < NCL_ * FOURU_; i += stride) {
        int k  = i >> 12;
        int jp = i & 4095;
        int src = ((jp & 3) << 10) + (jp >> 2);
        g_Wwperm[i] = W[((size_t)(k + D_) << 12) + src];
        if (k == 0) g_bperm[jp] = b[src];
    }
    // U transposed to [n=j'][k], split into 3 bf16 terms
    for (int i = tid0; i < FOURU_ * UNITS_; i += stride) {
        int jp = i >> 10;
        int k  = i & 1023;
        int src = ((jp & 3) << 10) + (jp >> 2);
        float v = U[((size_t)k << 12) + src];
        __nv_bfloat16 v1 = __float2bfloat16(v);
        float r1 = v - __bfloat162float(v1);
        __nv_bfloat16 v2 = __float2bfloat16(r1);
        float r2 = r1 - __bfloat162float(v2);
        g_Us[0][i] = v1;
        g_Us[1][i] = v2;
        g_Us[2][i] = __float2bfloat16(r2);
    }
    // Wx transposed to [n=j'][k], split into 3 bf16 terms
    for (int i = tid0; i < FOURU_ * D_; i += stride) {
        int jp = i >> 9;
        int k  = i & 511;
        int src = ((jp & 3) << 10) + (jp >> 2);
        float v = W[((size_t)k << 12) + src];
        __nv_bfloat16 v1 = __float2bfloat16(v);
        float r1 = v - __bfloat162float(v1);
        __nv_bfloat16 v2 = __float2bfloat16(r1);
        float r2 = r1 - __bfloat162float(v2);
        g_Wxs[0][i] = v1;
        g_Wxs[1][i] = v2;
        g_Wxs[2][i] = __float2bfloat16(r2);
    }
    // x split into 3 bf16 terms, [m][k] row-major (natural layout)
    for (size_t i = tid0; i < (size_t)B_ * T_ * D_; i += stride) {
        float v = x[i];
        __nv_bfloat16 v1 = __float2bfloat16(v);
        float r1 = v - __bfloat162float(v1);
        __nv_bfloat16 v2 = __float2bfloat16(r1);
        float r2 = r1 - __bfloat162float(v2);
        g_xs[0][i] = v1;
        g_xs[1][i] = v2;
        g_xs[2][i] = __float2bfloat16(r2);
    }
}

// ---------------- shared wmma GEMM config ----------------
// CTA tile M=64 x N=64, 8 warps as 2(m) x 4(n), warp tile 32x16.
// K in 32-wide stages, cp.async THREE-buffer pipeline, ONE barrier per stage.
// accA holds only the a1*b1 pair; accS the 5 small pairs; merged with one
// __fadd_rn per element. Chains bit-identical to R14 (passed rel_err = 0).
// NOTE: pair-index tables MUST be local const arrays (compile-time foldable).
// R13 used __constant__ arrays -> dynamic fragment indexing -> local spills.
#define SKT     32
#define APAD    40
#define A_PLANE (64 * APAD)            // 2560 bf16
#define B_PLANE (64 * APAD)
#define ABUF    (3 * A_PLANE)
#define BBUF    (3 * B_PLANE)
#define BUFELEM (ABUF + BBUF)          // 15360 bf16 = 30720 B
#define NBUF    3
#define SMEM_STEP (NBUF * BUFELEM * 2) // 92160 B (2 CTAs/SM: 184 KB < 228 KB)
#define STG_LD  68

// ---------------- precompute: Zx = x @ Wxperm via wmma split-6 ----------------
__global__ void __launch_bounds__(256, 2) precompute_mma_kernel() {
    extern __shared__ char smem[];
    __nv_bfloat16* sb = (__nv_bfloat16*)smem;
    uint32_t sb_addr = smem_u32(smem);

    int tid = threadIdx.x;
    int wid = tid >> 5;
    int wm = wid & 1;
    int wn = wid >> 1;
    int n0 = blockIdx.x * 64;
    int m0 = blockIdx.y * 64;

    wmma::fragment<wmma::accumulator, 16, 16, 16, float> accA[2], accS[2];
#pragma unroll
    for (int i = 0; i < 2; i++) {
        wmma::fill_fragment(accA[i], 0.0f);
        wmma::fill_fragment(accS[i], 0.0f);
    }

    auto load_tile = [&](int kt, int buf) {
        uint32_t base = sb_addr + (uint32_t)buf * (BUFELEM * 2);
#pragma unroll
        for (int i = 0; i < 6; i++) {
            int idx = i * 256 + tid;
            if (idx < 768) {
                int s = idx >> 8;
                int rem = idx & 255;
                int row = rem >> 2, kc = rem & 3;
                uint32_t dst = base + (uint32_t)(s * A_PLANE + row * APAD + kc * 8) * 2;
                const void* src = &g_xs[s][(size_t)(m0 + row) * D_ + kt * SKT + kc * 8];
                cp_async16(dst, src);
            } else {
                int bidx = idx - 768;
                int s = bidx >> 8;
                int rem = bidx & 255;
                int n = rem >> 2, kc = rem & 3;
                uint32_t dst = base + (uint32_t)(ABUF + s * B_PLANE + n * APAD + kc * 8) * 2;
                const void* src = &g_Wxs[s][(size_t)(n0 + n) * D_ + kt * SKT + kc * 8];
                cp_async16(dst, src);
            }
        }
    };

    // local const tables: compile-time foldable, fragments stay in registers
    const int si[5] = {0, 1, 1, 0, 2};
    const int sj[5] = {1, 0, 1, 2, 0};

    const int NKT = D_ / SKT;           // 16
    load_tile(0, 0);
    cp_commit();
    load_tile(1, 1);
    cp_commit();

    int cbuf = 0, lbuf = 2;
    for (int kt = 0; kt < NKT; kt++) {
        if (kt + 1 < NKT) cp_wait1(); else cp_wait0();
        __syncthreads();   // buf kt visible; everyone finished computing kt-1
        if (kt + 2 < NKT) {
            load_tile(kt + 2, lbuf);
            cp_commit();
        }

        const __nv_bfloat16* abase = sb + (size_t)cbuf * BUFELEM;
        const __nv_bfloat16* bbase = abase + ABUF;

#pragma unroll
        for (int ksub = 0; ksub < 2; ksub++) {
            wmma::fragment<wmma::matrix_a, 16, 16, 16, __nv_bfloat16, wmma::row_major> af[3][2];
            wmma::fragment<wmma::matrix_b, 16, 16, 16, __nv_bfloat16, wmma::col_major> bf[3];
#pragma unroll
            for (int s = 0; s < 3; s++) {
#pragma unroll
                for (int im = 0; im < 2; im++)
                    wmma::load_matrix_sync(af[s][im],
                        abase + s * A_PLANE + (wm * 32 + im * 16) * APAD + ksub * 16, APAD);
                wmma::load_matrix_sync(bf[s],
                    bbase + s * B_PLANE + (wn * 16) * APAD + ksub * 16, APAD);
            }
#pragma unroll
            for (int im = 0; im < 2; im++)
                wmma::mma_sync(accA[im], af[0][im], bf[0], accA[im]);
#pragma unroll
            for (int p = 0; p < 5; p++)
#pragma unroll
                for (int im = 0; im < 2; im++)
                    wmma::mma_sync(accS[im], af[si[p]][im], bf[sj[p]], accS[im]);
        }
        cbuf = (cbuf + 1 == NBUF) ? 0 : cbuf + 1;
        lbuf = (lbuf + 1 == NBUF) ? 0 : lbuf + 1;
    }
    __syncthreads();       // all compute done before stage area overwrites buffers

#pragma unroll
    for (int im = 0; im < 2; im++)
#pragma unroll
        for (int e = 0; e < accA[im].num_elements; e++)
            accA[im].x[e] = __fadd_rn(accA[im].x[e], accS[im].x[e]);

    float* stage = (float*)smem;
#pragma unroll
    for (int im = 0; im < 2; im++)
        wmma::store_matrix_sync(
            stage + (wm * 32 + im * 16) * STG_LD + wn * 16,
            accA[im], STG_LD, wmma::mem_row_major);
    __syncthreads();

#pragma unroll
    for (int it = 0; it < 4; it++) {
        int id = it * 256 + tid;
        int rrow = id >> 4;
        int qc = id & 15;
        int m = m0 + rrow;             // m = b*T + t
        int b = m >> 8;
        int t = m & 255;
        float4 v = *(const float4*)&stage[rrow * STG_LD + qc * 4];
        *(float4*)&g_Zx[((size_t)t * B_ + b) * FOURU_ + n0 + qc * 4] = v;
    }
}

// ---------------- step: wmma bf16 split-6 GEMM + fused gates epilogue ----------------
__global__ void __launch_bounds__(256, 2) step_mma_kernel(int t) {
    extern __shared__ char smem[];
    __nv_bfloat16* sb = (__nv_bfloat16*)smem;
    uint32_t sb_addr = smem_u32(smem);

    int tid = threadIdx.x;
    int wid = tid >> 5;
    int wm = wid & 1;
    int wn = wid >> 1;
    int n0 = blockIdx.x * 64;
    int m0 = blockIdx.y * 64;
    const __nv_bfloat16* hsrc = &g_hs[t & 1][0][0];
    const size_t HPLANE = (size_t)B_ * UNITS_;

    wmma::fragment<wmma::accumulator, 16, 16, 16, float> accA[2], accS[2];
#pragma unroll
    for (int i = 0; i < 2; i++) {
        wmma::fill_fragment(accA[i], 0.0f);
        wmma::fill_fragment(accS[i], 0.0f);
    }

    auto load_tile = [&](int kt, int buf) {
        uint32_t base = sb_addr + (uint32_t)buf * (BUFELEM * 2);
#pragma unroll
        for (int i = 0; i < 6; i++) {
            int idx = i * 256 + tid;
            if (idx < 768) {
                int s = idx >> 8;
                int rem = idx & 255;
                int row = rem >> 2, kc = rem & 3;
                uint32_t dst = base + (uint32_t)(s * A_PLANE + row * APAD + kc * 8) * 2;
                const void* src = hsrc + (size_t)s * HPLANE +
                                  (size_t)(m0 + row) * UNITS_ + kt * SKT + kc * 8;
                cp_async16(dst, src);
            } else {
                int bidx = idx - 768;
                int s = bidx >> 8;
                int rem = bidx & 255;
                int n = rem >> 2, kc = rem & 3;
                uint32_t dst = base + (uint32_t)(ABUF + s * B_PLANE + n * APAD + kc * 8) * 2;
                const void* src = &g_Us[s][(size_t)(n0 + n) * UNITS_ + kt * SKT + kc * 8];
                cp_async16(dst, src);
            }
        }
    };

    // local const tables: compile-time foldable, fragments stay in registers
    const int si[5] = {0, 1, 1, 0, 2};
    const int sj[5] = {1, 0, 1, 2, 0};

    const int NKT = UNITS_ / SKT;       // 32
    load_tile(0, 0);
    cp_commit();
    load_tile(1, 1);
    cp_commit();

    int cbuf = 0, lbuf = 2;
    for (int kt = 0; kt < NKT; kt++) {
        if (kt + 1 < NKT) cp_wait1(); else cp_wait0();
        __syncthreads();   // buf kt visible; everyone finished computing kt-1
        if (kt + 2 < NKT) {
            load_tile(kt + 2, lbuf);
            cp_commit();
        }

        const __nv_bfloat16* abase = sb + (size_t)cbuf * BUFELEM;
        const __nv_bfloat16* bbase = abase + ABUF;

#pragma unroll
        for (int ksub = 0; ksub < 2; ksub++) {
            wmma::fragment<wmma::matrix_a, 16, 16, 16, __nv_bfloat16, wmma::row_major> af[3][2];
            wmma::fragment<wmma::matrix_b, 16, 16, 16, __nv_bfloat16, wmma::col_major> bf[3];
#pragma unroll
            for (int s = 0; s < 3; s++) {
#pragma unroll
                for (int im = 0; im < 2; im++)
                    wmma::load_matrix_sync(af[s][im],
                        abase + s * A_PLANE + (wm * 32 + im * 16) * APAD + ksub * 16, APAD);
                wmma::load_matrix_sync(bf[s],
                    bbase + s * B_PLANE + (wn * 16) * APAD + ksub * 16, APAD);
            }
            // main term -> accA (bit-identical chain to R14)
#pragma unroll
            for (int im = 0; im < 2; im++)
                wmma::mma_sync(accA[im], af[0][im], bf[0], accA[im]);
            // 5 small terms -> accS
#pragma unroll
            for (int p = 0; p < 5; p++)
#pragma unroll
                for (int im = 0; im < 2; im++)
                    wmma::mma_sync(accS[im], af[si[p]][im], bf[sj[p]], accS[im]);
        }
        cbuf = (cbuf + 1 == NBUF) ? 0 : cbuf + 1;
        lbuf = (lbuf + 1 == NBUF) ? 0 : lbuf + 1;
    }
    __syncthreads();       // all compute done before stage area overwrites buffers

#pragma unroll
    for (int im = 0; im < 2; im++)
#pragma unroll
        for (int e = 0; e < accA[im].num_elements; e++)
            accA[im].x[e] = __fadd_rn(accA[im].x[e], accS[im].x[e]);

    float* stage = (float*)smem;
#pragma unroll
    for (int im = 0; im < 2; im++)
        wmma::store_matrix_sync(
            stage + (wm * 32 + im * 16) * STG_LD + wn * 16,
            accA[im], STG_LD, wmma::mem_row_major);
    __syncthreads();

    float* h_out = (t & 1) ? g_h0 : g_h1;
    int pnew = (t + 1) & 1;
#pragma unroll
    for (int it = 0; it < 4; it++) {
        int id = it * 256 + tid;
        int rrow = id >> 4;
        int qc = id & 15;
        int bat = m0 + rrow;
        int idx = g_idx[bat];
        int jb = n0 + qc * 4;

        float4 zx4 = *(const float4*)&g_Zx[((size_t)t * B_ + bat) * FOURU_ + jb];
        float ins[4] = {zx4.x, zx4.y, zx4.z, zx4.w};
        if (idx >= 0) {
            float4 ww = *(const float4*)&g_Wwperm[(size_t)idx * FOURU_ + jb];
            ins[0] = __fadd_rn(ins[0], ww.x);
            ins[1] = __fadd_rn(ins[1], ww.y);
            ins[2] = __fadd_rn(ins[2], ww.z);
            ins[3] = __fadd_rn(ins[3], ww.w);
        }
        float4 b4 = *(const float4*)&g_bperm[jb];
        float bv[4] = {b4.x, b4.y, b4.z, b4.w};
        float4 ac4 = *(const float4*)&stage[rrow * STG_LD + qc * 4];
        float av[4] = {ac4.x, ac4.y, ac4.z, ac4.w};
        float z[4];
#pragma unroll
        for (int g = 0; g < 4; g++)
            z[g] = __fadd_rn(__fadd_rn(ins[g], av[g]), bv[g]);

        int u = jb >> 2;
        float cold = g_c[bat * UNITS_ + u];
        float m1 = __fmul_rn(hsig(z[1]), cold);
        float m2 = __fmul_rn(hsig(z[0]), tanh_xla(z[2]));
        float cn = __fadd_rn(m1, m2);
        float hn = __fmul_rn(hsig(z[3]), tanh_xla(cn));
        g_c[bat * UNITS_ + u] = cn;
        h_out[bat * UNITS_ + u] = hn;

        __nv_bfloat16 h1 = __float2bfloat16(hn);
        float r1 = hn - __bfloat162float(h1);
        __nv_bfloat16 h2 = __float2bfloat16(r1);
        float r2 = r1 - __bfloat162float(h2);
        __nv_bfloat16 h3 = __float2bfloat16(r2);
        g_hs[pnew][0][bat * UNITS_ + u] = h1;
        g_hs[pnew][1][bat * UNITS_ + u] = h2;
        g_hs[pnew][2][bat * UNITS_ + u] = h3;
    }
}

// ---------------- logits partials: h_new @ Wout, 64x64 tiles, K split x8 ----------------
#define BK 16
#define LBM 64
#define LBN 64
#define LASTRIDE (LBM + 4)

__global__ void __launch_bounds__(256) logits_kernel(const float* __restrict__ Wout, int t) {
    const float* __restrict__ h = (t & 1) ? g_h0 : g_h1;   // h_new written by step t

    __shared__ float As[BK][LASTRIDE];
    __shared__ float Bs[BK][LBN];
    int tid = threadIdx.x;
    int tx = tid & 15, ty = tid >> 4;
    int m0 = blockIdx.y * LBM;
    int n0 = blockIdx.x * LBN;
    int kc = blockIdx.z;
    int kbeg = kc * 128;

    float acc[4][4];
#pragma unroll
    for (int i = 0; i < 4; i++)
#pragma unroll
        for (int j = 0; j < 4; j++) acc[i][j] = 0.0f;

    for (int k0 = kbeg; k0 < kbeg + 128; k0 += BK) {
        {
            int row = tid >> 2, c4 = tid & 3;
            float4 v = *(const float4*)&h[(size_t)(m0 + row) * UNITS_ + k0 + c4 * 4];
            As[c4 * 4 + 0][row] = v.x;
            As[c4 * 4 + 1][row] = v.y;
            As[c4 * 4 + 2][row] = v.z;
            As[c4 * 4 + 3][row] = v.w;
        }
        {
            int row = tid >> 4, c4 = tid & 15;
            *(float4*)&Bs[row][c4 * 4] =
                *(const float4*)&Wout[(size_t)(k0 + row) * NCL_ + n0 + c4 * 4];
        }
        __syncthreads();
#pragma unroll
        for (int kk = 0; kk < BK; kk++) {
            float4 a4 = *(const float4*)&As[kk][ty * 4];
            float4 b4 = *(const float4*)&Bs[kk][tx * 4];
            float a[4] = {a4.x, a4.y, a4.z, a4.w};
            float bb[4] = {b4.x, b4.y, b4.z, b4.w};
#pragma unroll
            for (int i = 0; i < 4; i++)
#pragma unroll
                for (int j = 0; j < 4; j++) acc[i][j] = fmaf(a[i], bb[j], acc[i][j]);
        }
        __syncthreads();
    }

#pragma unroll
    for (int i = 0; i < 4; i++) {
        int m = m0 + ty * 4 + i;
        float* dst = &g_lpart[((size_t)kc * B_ + m) * NCL_ + n0 + tx * 4];
        *(float4*)dst = make_float4(acc[i][0], acc[i][1], acc[i][2], acc[i][3]);
    }
}

// ---------------- reduce partials + bias, argmax (tie -> lowest index) ----------------
__global__ void __launch_bounds__(256) argmax_kernel(const float* __restrict__ bout,
                                                     float* __restrict__ out, int t) {
    int b = blockIdx.x;
    int tid = threadIdx.x;
    unsigned long long best = 0ull;
    for (int n = tid; n < NCL_; n += 256) {
        float l = 0.0f;
#pragma unroll
        for (int kc = 0; kc < 8; kc++)
            l = __fadd_rn(l, g_lpart[((size_t)kc * B_ + b) * NCL_ + n]);
        l = __fadd_rn(l, bout[n]);
        unsigned u = __float_as_uint(l);
        u = (u & 0x80000000u) ? ~u : (u | 0x80000000u);
        unsigned long long key = ((unsigned long long)u << 32) | (unsigned)(NCL_ - 1 - n);
        best = best > key ? best : key;
    }
    __shared__ unsigned long long red[256];
    red[tid] = best;
    __syncthreads();
    for (int s = 128; s > 0; s >>= 1) {
        if (tid < s) red[tid] = red[tid] > red[tid + s] ? red[tid] : red[tid + s];
        __syncthreads();
    }
    if (tid == 0) {
        int idx = (NCL_ - 1) - (int)(red[0] & 0xffffffffu);
        g_idx[b] = idx;
        out[(size_t)b * T_ + t] = (float)idx;   // output dtype: float32
    }
}

// ---------------- launch (3 + 256*3 = 771 graph nodes, proven infra-safe) ----------------
extern "C" void kernel_launch(void* const* d_in, const int* in_sizes, int n_in,
                              void* d_out, int out_size) {
    (void)out_size;
    const float *x = 0, *W = 0, *U = 0, *b = 0, *Wout = 0, *bout = 0;
    const float* big[2] = {0, 0};
    int nbig = 0;
    for (int i = 0; i < n_in; i++) {
        switch (in_sizes[i]) {
            case 33554432: x    = (const float*)d_in[i]; break;  // 256*256*512
            case 524288:   Wout = (const float*)d_in[i]; break;  // 1024*512
            case 4096:     b    = (const float*)d_in[i]; break;
            case 512:      bout = (const float*)d_in[i]; break;
            case 4194304:  if (nbig < 2) big[nbig++] = (const float*)d_in[i]; break;
            default: break;
        }
    }
    W = big[0];
    U = big[1];
    float* out = (float*)d_out;

    cudaFuncSetAttribute(step_mma_kernel, cudaFuncAttributeMaxDynamicSharedMemorySize, SMEM_STEP);
    cudaFuncSetAttribute(precompute_mma_kernel, cudaFuncAttributeMaxDynamicSharedMemorySize, SMEM_STEP);

    init_kernel<<<512, 256>>>();
    permute_kernel<<<2048, 256>>>(W, U, b, x);
    precompute_mma_kernel<<<dim3(FOURU_ / 64, (B_ * T_) / 64), 256, SMEM_STEP>>>();

    for (int t = 0; t < T_; t++) {
        step_mma_kernel<<<dim3(FOURU_ / 64, B_ / 64), 256, SMEM_STEP>>>(t);
        logits_kernel<<<dim3(NCL_ / LBN, B_ / LBM, 8), 256>>>(Wout, t);
        argmax_kernel<<<B_, 256>>>(bout, out, t);
    }
}

// round 16
// speedup vs baseline: 2.2698x; 1.0639x over previous
#include <cuda_runtime.h>
#include <cuda_bf16.h>
#include <mma.h>
#include <math.h>
#include <stdint.h>

using namespace nvcuda;

#define B_      256
#define T_      256
#define D_      512
#define UNITS_  1024
#define NCL_    512
#define FOURU_  4096

// ---------------- static device scratch (no allocs allowed) ----------------
__device__ float g_Zx[(size_t)T_ * B_ * FOURU_];     // [t][b][j'] = x_t @ Wx (permuted), NO bias
__device__ float g_Wwperm[(size_t)NCL_ * FOURU_];
__device__ float g_bperm[FOURU_];
__device__ __nv_bfloat16 g_Us[3][(size_t)FOURU_ * UNITS_];   // U splits, [n=j'][k] (K-major)
__device__ __nv_bfloat16 g_Wxs[3][(size_t)FOURU_ * D_];      // Wx splits, [n=j'][k] (K-major)
__device__ __nv_bfloat16 g_xs[3][(size_t)B_ * T_ * D_];      // x splits, [m=b*T+t][k]
__device__ __nv_bfloat16 g_hs[2][3][B_ * UNITS_];            // h splits ping-pong [b][k]
__device__ float g_h0[B_ * UNITS_];
__device__ float g_h1[B_ * UNITS_];
__device__ float g_c[B_ * UNITS_];
__device__ int   g_idx[B_];
__device__ float g_lpart[(size_t)8 * B_ * NCL_];     // logit partials

// ---------------- numerics helpers (bit-matching XLA) ----------------
__device__ __forceinline__ float hsig(float z) {
    float t = __fadd_rn(__fmul_rn(0.2f, z), 0.5f);
    return fminf(fmaxf(t, 0.0f), 1.0f);
}
__device__ __forceinline__ float tanh_xla(float x) {
    float ax = fabsf(x);
    if (ax < 0.0004f) return x;
    float xc = fminf(fmaxf(x, -9.0f), 9.0f);
    float x2 = __fmul_rn(xc, xc);
    float p = -2.76076847742355e-16f;
    p = fmaf(p, x2, 2.00018790482477e-13f);
    p = fmaf(p, x2, -8.60467152213735e-11f);
    p = fmaf(p, x2, 5.12229709037114e-08f);
    p = fmaf(p, x2, 1.48572235717979e-05f);
    p = fmaf(p, x2, 6.37261928875436e-04f);
    p = fmaf(p, x2, 4.89352455891786e-03f);
    float num = __fmul_rn(xc, p);
    float q = 1.19825839466702e-06f;
    q = fmaf(q, x2, 1.18534705686654e-04f);
    q = fmaf(q, x2, 2.26843463243900e-03f);
    q = fmaf(q, x2, 4.89352518554385e-03f);
    return __fdiv_rn(num, q);
}

__device__ __forceinline__ uint32_t smem_u32(const void* p) {
    uint32_t a;
    asm("{ .reg .u64 t; cvta.to.shared.u64 t, %1; cvt.u32.u64 %0, t; }" : "=r"(a) : "l"(p));
    return a;
}
__device__ __forceinline__ void cp_async16(uint32_t dst, const void* src) {
    asm volatile("cp.async.cg.shared.global [%0], [%1], 16;" :: "r"(dst), "l"(src));
}
__device__ __forceinline__ void cp_commit() {
    asm volatile("cp.async.commit_group;");
}
__device__ __forceinline__ void cp_wait1() {
    asm volatile("cp.async.wait_group 1;");
}
__device__ __forceinline__ void cp_wait0() {
    asm volatile("cp.async.wait_group 0;");
}

// ---------------- init ----------------
__global__ void init_kernel() {
    int stride = gridDim.x * blockDim.x;
    for (int i = blockIdx.x * blockDim.x + threadIdx.x; i < B_ * UNITS_; i += stride) {
        g_h0[i] = 0.0f;
        g_c[i] = 0.0f;
        g_hs[0][0][i] = __float2bfloat16(0.0f);
        g_hs[0][1][i] = __float2bfloat16(0.0f);
        g_hs[0][2][i] = __float2bfloat16(0.0f);
        if (i < B_) g_idx[i] = -1;
    }
}

// ---------------- permute weights + build all bf16 splits ----------------
__global__ void permute_kernel(const float* __restrict__ W,
                               const float* __restrict__ U,
                               const float* __restrict__ b,
                               const float* __restrict__ x) {
    int stride = gridDim.x * blockDim.x;
    int tid0 = blockIdx.x * blockDim.x + threadIdx.x;
    // Ww / bias, gate-interleaved columns j' = 4u + g
    for (int i = tid0; i < NCL_ * FOURU_; i += stride) {
        int k  = i >> 12;
        int jp = i & 4095;
        int src = ((jp & 3) << 10) + (jp >> 2);
        g_Wwperm[i] = W[((size_t)(k + D_) << 12) + src];
        if (k == 0) g_bperm[jp] = b[src];
    }
    // U transposed to [n=j'][k], split into 3 bf16 terms
    for (int i = tid0; i < FOURU_ * UNITS_; i += stride) {
        int jp = i >> 10;
        int k  = i & 1023;
        int src = ((jp & 3) << 10) + (jp >> 2);
        float v = U[((size_t)k << 12) + src];
        __nv_bfloat16 v1 = __float2bfloat16(v);
        float r1 = v - __bfloat162float(v1);
        __nv_bfloat16 v2 = __float2bfloat16(r1);
        float r2 = r1 - __bfloat162float(v2);
        g_Us[0][i] = v1;
        g_Us[1][i] = v2;
        g_Us[2][i] = __float2bfloat16(r2);
    }
    // Wx transposed to [n=j'][k], split into 3 bf16 terms
    for (int i = tid0; i < FOURU_ * D_; i += stride) {
        int jp = i >> 9;
        int k  = i & 511;
        int src = ((jp & 3) << 10) + (jp >> 2);
        float v = W[((size_t)k << 12) + src];
        __nv_bfloat16 v1 = __float2bfloat16(v);
        float r1 = v - __bfloat162float(v1);
        __nv_bfloat16 v2 = __float2bfloat16(r1);
        float r2 = r1 - __bfloat162float(v2);
        g_Wxs[0][i] = v1;
        g_Wxs[1][i] = v2;
        g_Wxs[2][i] = __float2bfloat16(r2);
    }
    // x split into 3 bf16 terms, [m][k] row-major (natural layout)
    for (size_t i = tid0; i < (size_t)B_ * T_ * D_; i += stride) {
        float v = x[i];
        __nv_bfloat16 v1 = __float2bfloat16(v);
        float r1 = v - __bfloat162float(v1);
        __nv_bfloat16 v2 = __float2bfloat16(r1);
        float r2 = r1 - __bfloat162float(v2);
        g_xs[0][i] = v1;
        g_xs[1][i] = v2;
        g_xs[2][i] = __float2bfloat16(r2);
    }
}

// ---------------- shared wmma GEMM config ----------------
// CTA tile M=64 x N=64, 8 warps as 2(m) x 4(n), warp tile 32x16.
// accA = a1*b1 pair only; accS = 5 small pairs; merged with one __fadd_rn.
// Accumulation chains BIT-IDENTICAL to R14/R15 (passed rel_err = 0).
// NOTE: pair-index tables MUST be local const arrays (R13 spill lesson).
#define SKT     32
#define APAD    40
#define A_PLANE (64 * APAD)            // 2560 bf16
#define B_PLANE (64 * APAD)
#define ABUF    (3 * A_PLANE)
#define BBUF    (3 * B_PLANE)
#define BUFELEM (ABUF + BBUF)          // 15360 bf16 = 30720 B
#define STG_LD  68

// precompute: 3-buffer pipeline (R15, kept)
#define SMEM_PRE (3 * BUFELEM * 2)     // 92160 B

// step: 2-buffer pipeline + epilogue prefetch region
#define PRE_ZX   (2 * BUFELEM * 2)     // 61440: Zx tile 64x64 f32 (16384 B)
#define PRE_WW   (PRE_ZX + 16384)      // 77824: Ww gather 64x64 f32 (16384 B)
#define PRE_C    (PRE_WW + 16384)      // 94208: c slice 64x16 f32 (4096 B)
#define PRE_B    (PRE_C + 4096)        // 98304: bias slice 64 f32 (256 B)
#define SMEM_STEP (PRE_B + 256)        // 98560 B (2 CTAs/SM: 197120 <= 227 KB)

// ---------------- precompute: Zx = x @ Wxperm via wmma split-6 (R15 form) ----------------
__global__ void __launch_bounds__(256, 2) precompute_mma_kernel() {
    extern __shared__ char smem[];
    __nv_bfloat16* sb = (__nv_bfloat16*)smem;
    uint32_t sb_addr = smem_u32(smem);

    int tid = threadIdx.x;
    int wid = tid >> 5;
    int wm = wid & 1;
    int wn = wid >> 1;
    int n0 = blockIdx.x * 64;
    int m0 = blockIdx.y * 64;

    wmma::fragment<wmma::accumulator, 16, 16, 16, float> accA[2], accS[2];
#pragma unroll
    for (int i = 0; i < 2; i++) {
        wmma::fill_fragment(accA[i], 0.0f);
        wmma::fill_fragment(accS[i], 0.0f);
    }

    auto load_tile = [&](int kt, int buf) {
        uint32_t base = sb_addr + (uint32_t)buf * (BUFELEM * 2);
#pragma unroll
        for (int i = 0; i < 6; i++) {
            int idx = i * 256 + tid;
            if (idx < 768) {
                int s = idx >> 8;
                int rem = idx & 255;
                int row = rem >> 2, kc = rem & 3;
                uint32_t dst = base + (uint32_t)(s * A_PLANE + row * APAD + kc * 8) * 2;
                const void* src = &g_xs[s][(size_t)(m0 + row) * D_ + kt * SKT + kc * 8];
                cp_async16(dst, src);
            } else {
                int bidx = idx - 768;
                int s = bidx >> 8;
                int rem = bidx & 255;
                int n = rem >> 2, kc = rem & 3;
                uint32_t dst = base + (uint32_t)(ABUF + s * B_PLANE + n * APAD + kc * 8) * 2;
                const void* src = &g_Wxs[s][(size_t)(n0 + n) * D_ + kt * SKT + kc * 8];
                cp_async16(dst, src);
            }
        }
    };

    const int si[5] = {0, 1, 1, 0, 2};
    const int sj[5] = {1, 0, 1, 2, 0};

    const int NKT = D_ / SKT;           // 16
    load_tile(0, 0);
    cp_commit();
    load_tile(1, 1);
    cp_commit();

    int cbuf = 0, lbuf = 2;
    for (int kt = 0; kt < NKT; kt++) {
        if (kt + 1 < NKT) cp_wait1(); else cp_wait0();
        __syncthreads();
        if (kt + 2 < NKT) {
            load_tile(kt + 2, lbuf);
            cp_commit();
        }

        const __nv_bfloat16* abase = sb + (size_t)cbuf * BUFELEM;
        const __nv_bfloat16* bbase = abase + ABUF;

#pragma unroll
        for (int ksub = 0; ksub < 2; ksub++) {
            wmma::fragment<wmma::matrix_a, 16, 16, 16, __nv_bfloat16, wmma::row_major> af[3][2];
            wmma::fragment<wmma::matrix_b, 16, 16, 16, __nv_bfloat16, wmma::col_major> bf[3];
#pragma unroll
            for (int s = 0; s < 3; s++) {
#pragma unroll
                for (int im = 0; im < 2; im++)
                    wmma::load_matrix_sync(af[s][im],
                        abase + s * A_PLANE + (wm * 32 + im * 16) * APAD + ksub * 16, APAD);
                wmma::load_matrix_sync(bf[s],
                    bbase + s * B_PLANE + (wn * 16) * APAD + ksub * 16, APAD);
            }
#pragma unroll
            for (int im = 0; im < 2; im++)
                wmma::mma_sync(accA[im], af[0][im], bf[0], accA[im]);
#pragma unroll
            for (int p = 0; p < 5; p++)
#pragma unroll
                for (int im = 0; im < 2; im++)
                    wmma::mma_sync(accS[im], af[si[p]][im], bf[sj[p]], accS[im]);
        }
        cbuf = (cbuf + 1 == 3) ? 0 : cbuf + 1;
        lbuf = (lbuf + 1 == 3) ? 0 : lbuf + 1;
    }
    __syncthreads();

#pragma unroll
    for (int im = 0; im < 2; im++)
#pragma unroll
        for (int e = 0; e < accA[im].num_elements; e++)
            accA[im].x[e] = __fadd_rn(accA[im].x[e], accS[im].x[e]);

    float* stage = (float*)smem;
#pragma unroll
    for (int im = 0; im < 2; im++)
        wmma::store_matrix_sync(
            stage + (wm * 32 + im * 16) * STG_LD + wn * 16,
            accA[im], STG_LD, wmma::mem_row_major);
    __syncthreads();

#pragma unroll
    for (int it = 0; it < 4; it++) {
        int id = it * 256 + tid;
        int rrow = id >> 4;
        int qc = id & 15;
        int m = m0 + rrow;             // m = b*T + t
        int b = m >> 8;
        int t = m & 255;
        float4 v = *(const float4*)&stage[rrow * STG_LD + qc * 4];
        *(float4*)&g_Zx[((size_t)t * B_ + b) * FOURU_ + n0 + qc * 4] = v;
    }
}

// ---------------- step: wmma split-6 GEMM, 2-buf + epilogue smem prefetch ----------------
__global__ void __launch_bounds__(256, 2) step_mma_kernel(int t) {
    extern __shared__ char smem[];
    __nv_bfloat16* sb = (__nv_bfloat16*)smem;
    uint32_t sb_addr = smem_u32(smem);

    int tid = threadIdx.x;
    int wid = tid >> 5;
    int wm = wid & 1;
    int wn = wid >> 1;
    int n0 = blockIdx.x * 64;
    int m0 = blockIdx.y * 64;
    const __nv_bfloat16* hsrc = &g_hs[t & 1][0][0];
    const size_t HPLANE = (size_t)B_ * UNITS_;

    wmma::fragment<wmma::accumulator, 16, 16, 16, float> accA[2], accS[2];
#pragma unroll
    for (int i = 0; i < 2; i++) {
        wmma::fill_fragment(accA[i], 0.0f);
        wmma::fill_fragment(accS[i], 0.0f);
    }

    auto load_tile = [&](int kt, int buf) {
        uint32_t base = sb_addr + (uint32_t)buf * (BUFELEM * 2);
#pragma unroll
        for (int i = 0; i < 6; i++) {
            int idx = i * 256 + tid;
            if (idx < 768) {
                int s = idx >> 8;
                int rem = idx & 255;
                int row = rem >> 2, kc = rem & 3;
                uint32_t dst = base + (uint32_t)(s * A_PLANE + row * APAD + kc * 8) * 2;
                const void* src = hsrc + (size_t)s * HPLANE +
                                  (size_t)(m0 + row) * UNITS_ + kt * SKT + kc * 8;
                cp_async16(dst, src);
            } else {
                int bidx = idx - 768;
                int s = bidx >> 8;
                int rem = bidx & 255;
                int n = rem >> 2, kc = rem & 3;
                uint32_t dst = base + (uint32_t)(ABUF + s * B_PLANE + n * APAD + kc * 8) * 2;
                const void* src = &g_Us[s][(size_t)(n0 + n) * UNITS_ + kt * SKT + kc * 8];
                cp_async16(dst, src);
            }
        }
    };

    const int si[5] = {0, 1, 1, 0, 2};
    const int sj[5] = {1, 0, 1, 2, 0};

    // ---- epilogue prefetch: Zx tile, Ww gather, c slice, bias (joins group 0)
    {
#pragma unroll
        for (int i = 0; i < 4; i++) {              // Zx: 1024 chunks
            int ch = i * 256 + tid;
            int r = ch >> 4, c16 = ch & 15;
            cp_async16(sb_addr + PRE_ZX + r * 256 + c16 * 16,
                       &g_Zx[((size_t)t * B_ + m0 + r) * FOURU_ + n0 + c16 * 4]);
        }
#pragma unroll
        for (int i = 0; i < 4; i++) {              // Ww: 1024 chunks (guarded by idx)
            int ch = i * 256 + tid;
            int r = ch >> 4, c16 = ch & 15;
            int idx = g_idx[m0 + r];
            if (idx >= 0)
                cp_async16(sb_addr + PRE_WW + r * 256 + c16 * 16,
                           &g_Wwperm[(size_t)idx * FOURU_ + n0 + c16 * 4]);
        }
        {                                          // c: 256 chunks
            int r = tid >> 2, c16 = tid & 3;
            cp_async16(sb_addr + PRE_C + r * 64 + c16 * 16,
                       &g_c[(m0 + r) * UNITS_ + (n0 >> 2) + c16 * 4]);
        }
        if (tid < 16)                              // bias: 16 chunks
            cp_async16(sb_addr + PRE_B + tid * 16, &g_bperm[n0 + tid * 4]);
    }

    const int NKT = UNITS_ / SKT;       // 32
    load_tile(0, 0);
    cp_commit();                        // group 0 = prefetch + tile0

    for (int kt = 0; kt < NKT; kt++) {
        int buf = kt & 1;
        if (kt + 1 < NKT) {
            load_tile(kt + 1, buf ^ 1);
            cp_commit();
            cp_wait1();
        } else {
            cp_wait0();
        }
        __syncthreads();

        const __nv_bfloat16* abase = sb + (size_t)buf * BUFELEM;
        const __nv_bfloat16* bbase = abase + ABUF;

#pragma unroll
        for (int ksub = 0; ksub < 2; ksub++) {
            wmma::fragment<wmma::matrix_a, 16, 16, 16, __nv_bfloat16, wmma::row_major> af[3][2];
            wmma::fragment<wmma::matrix_b, 16, 16, 16, __nv_bfloat16, wmma::col_major> bf[3];
#pragma unroll
            for (int s = 0; s < 3; s++) {
#pragma unroll
                for (int im = 0; im < 2; im++)
                    wmma::load_matrix_sync(af[s][im],
                        abase + s * A_PLANE + (wm * 32 + im * 16) * APAD + ksub * 16, APAD);
                wmma::load_matrix_sync(bf[s],
                    bbase + s * B_PLANE + (wn * 16) * APAD + ksub * 16, APAD);
            }
            // main term -> accA (bit-identical chain to R14/R15)
#pragma unroll
            for (int im = 0; im < 2; im++)
                wmma::mma_sync(accA[im], af[0][im], bf[0], accA[im]);
            // 5 small terms -> accS
#pragma unroll
            for (int p = 0; p < 5; p++)
#pragma unroll
                for (int im = 0; im < 2; im++)
                    wmma::mma_sync(accS[im], af[si[p]][im], bf[sj[p]], accS[im]);
        }
    }

#pragma unroll
    for (int im = 0; im < 2; im++)
#pragma unroll
        for (int e = 0; e < accA[im].num_elements; e++)
            accA[im].x[e] = __fadd_rn(accA[im].x[e], accS[im].x[e]);

    // stage area [0, 17408) lies in buffer 0; last compute used buffer 1
    // (NKT even), and every warp passed the kt=31 barrier -> buffer 0 free.
    float* stage = (float*)smem;
#pragma unroll
    for (int im = 0; im < 2; im++)
        wmma::store_matrix_sync(
            stage + (wm * 32 + im * 16) * STG_LD + wn * 16,
            accA[im], STG_LD, wmma::mem_row_major);
    __syncthreads();

    float* h_out = (t & 1) ? g_h0 : g_h1;
    int pnew = (t + 1) & 1;
#pragma unroll
    for (int it = 0; it < 4; it++) {
        int id = it * 256 + tid;
        int rrow = id >> 4;
        int qc = id & 15;
        int bat = m0 + rrow;
        int idx = g_idx[bat];
        int jb = n0 + qc * 4;

        float4 zx4 = *(const float4*)(smem + PRE_ZX + rrow * 256 + qc * 16);
        float ins[4] = {zx4.x, zx4.y, zx4.z, zx4.w};
        if (idx >= 0) {
            float4 ww = *(const float4*)(smem + PRE_WW + rrow * 256 + qc * 16);
            ins[0] = __fadd_rn(ins[0], ww.x);
            ins[1] = __fadd_rn(ins[1], ww.y);
            ins[2] = __fadd_rn(ins[2], ww.z);
            ins[3] = __fadd_rn(ins[3], ww.w);
        }
        float4 b4 = *(const float4*)(smem + PRE_B + qc * 16);
        float bv[4] = {b4.x, b4.y, b4.z, b4.w};
        float4 ac4 = *(const float4*)&stage[rrow * STG_LD + qc * 4];
        float av[4] = {ac4.x, ac4.y, ac4.z, ac4.w};
        float z[4];
#pragma unroll
        for (int g = 0; g < 4; g++)
            z[g] = __fadd_rn(__fadd_rn(ins[g], av[g]), bv[g]);

        int u = jb >> 2;
        float cold = *(const float*)(smem + PRE_C + rrow * 64 + qc * 4);
        float m1 = __fmul_rn(hsig(z[1]), cold);
        float m2 = __fmul_rn(hsig(z[0]), tanh_xla(z[2]));
        float cn = __fadd_rn(m1, m2);
        float hn = __fmul_rn(hsig(z[3]), tanh_xla(cn));
        g_c[bat * UNITS_ + u] = cn;
        h_out[bat * UNITS_ + u] = hn;

        __nv_bfloat16 h1 = __float2bfloat16(hn);
        float r1 = hn - __bfloat162float(h1);
        __nv_bfloat16 h2 = __float2bfloat16(r1);
        float r2 = r1 - __bfloat162float(h2);
        __nv_bfloat16 h3 = __float2bfloat16(r2);
        g_hs[pnew][0][bat * UNITS_ + u] = h1;
        g_hs[pnew][1][bat * UNITS_ + u] = h2;
        g_hs[pnew][2][bat * UNITS_ + u] = h3;
    }
}

// ---------------- logits partials: h_new @ Wout, 64x64 tiles, K split x8 ----------------
#define BK 16
#define LBM 64
#define LBN 64
#define LASTRIDE (LBM + 4)

__global__ void __launch_bounds__(256) logits_kernel(const float* __restrict__ Wout, int t) {
    const float* __restrict__ h = (t & 1) ? g_h0 : g_h1;   // h_new written by step t

    __shared__ float As[BK][LASTRIDE];
    __shared__ float Bs[BK][LBN];
    int tid = threadIdx.x;
    int tx = tid & 15, ty = tid >> 4;
    int m0 = blockIdx.y * LBM;
    int n0 = blockIdx.x * LBN;
    int kc = blockIdx.z;
    int kbeg = kc * 128;

    float acc[4][4];
#pragma unroll
    for (int i = 0; i < 4; i++)
#pragma unroll
        for (int j = 0; j < 4; j++) acc[i][j] = 0.0f;

    for (int k0 = kbeg; k0 < kbeg + 128; k0 += BK) {
        {
            int row = tid >> 2, c4 = tid & 3;
            float4 v = *(const float4*)&h[(size_t)(m0 + row) * UNITS_ + k0 + c4 * 4];
            As[c4 * 4 + 0][row] = v.x;
            As[c4 * 4 + 1][row] = v.y;
            As[c4 * 4 + 2][row] = v.z;
            As[c4 * 4 + 3][row] = v.w;
        }
        {
            int row = tid >> 4, c4 = tid & 15;
            *(float4*)&Bs[row][c4 * 4] =
                *(const float4*)&Wout[(size_t)(k0 + row) * NCL_ + n0 + c4 * 4];
        }
        __syncthreads();
#pragma unroll
        for (int kk = 0; kk < BK; kk++) {
            float4 a4 = *(const float4*)&As[kk][ty * 4];
            float4 b4 = *(const float4*)&Bs[kk][tx * 4];
            float a[4] = {a4.x, a4.y, a4.z, a4.w};
            float bb[4] = {b4.x, b4.y, b4.z, b4.w};
#pragma unroll
            for (int i = 0; i < 4; i++)
#pragma unroll
                for (int j = 0; j < 4; j++) acc[i][j] = fmaf(a[i], bb[j], acc[i][j]);
        }
        __syncthreads();
    }

#pragma unroll
    for (int i = 0; i < 4; i++) {
        int m = m0 + ty * 4 + i;
        float* dst = &g_lpart[((size_t)kc * B_ + m) * NCL_ + n0 + tx * 4];
        *(float4*)dst = make_float4(acc[i][0], acc[i][1], acc[i][2], acc[i][3]);
    }
}

// ---------------- reduce partials + bias, argmax (tie -> lowest index) ----------------
__global__ void __launch_bounds__(256) argmax_kernel(const float* __restrict__ bout,
                                                     float* __restrict__ out, int t) {
    int b = blockIdx.x;
    int tid = threadIdx.x;
    unsigned long long best = 0ull;
    for (int n = tid; n < NCL_; n += 256) {
        float l = 0.0f;
#pragma unroll
        for (int kc = 0; kc < 8; kc++)
            l = __fadd_rn(l, g_lpart[((size_t)kc * B_ + b) * NCL_ + n]);
        l = __fadd_rn(l, bout[n]);
        unsigned u = __float_as_uint(l);
        u = (u & 0x80000000u) ? ~u : (u | 0x80000000u);
        unsigned long long key = ((unsigned long long)u << 32) | (unsigned)(NCL_ - 1 - n);
        best = best > key ? best : key;
    }
    __shared__ unsigned long long red[256];
    red[tid] = best;
    __syncthreads();
    for (int s = 128; s > 0; s >>= 1) {
        if (tid < s) red[tid] = red[tid] > red[tid + s] ? red[tid] : red[tid + s];
        __syncthreads();
    }
    if (tid == 0) {
        int idx = (NCL_ - 1) - (int)(red[0] & 0xffffffffu);
        g_idx[b] = idx;
        out[(size_t)b * T_ + t] = (float)idx;   // output dtype: float32
    }
}

// ---------------- launch (3 + 256*3 = 771 graph nodes, proven infra-safe) ----------------
extern "C" void kernel_launch(void* const* d_in, const int* in_sizes, int n_in,
                              void* d_out, int out_size) {
    (void)out_size;
    const float *x = 0, *W = 0, *U = 0, *b = 0, *Wout = 0, *bout = 0;
    const float* big[2] = {0, 0};
    int nbig = 0;
    for (int i = 0; i < n_in; i++) {
        switch (in_sizes[i]) {
            case 33554432: x    = (const float*)d_in[i]; break;  // 256*256*512
            case 524288:   Wout = (const float*)d_in[i]; break;  // 1024*512
            case 4096:     b    = (const float*)d_in[i]; break;
            case 512:      bout = (const float*)d_in[i]; break;
            case 4194304:  if (nbig < 2) big[nbig++] = (const float*)d_in[i]; break;
            default: break;
        }
    }
    W = big[0];
    U = big[1];
    float* out = (float*)d_out;

    cudaFuncSetAttribute(step_mma_kernel, cudaFuncAttributeMaxDynamicSharedMemorySize, SMEM_STEP);
    cudaFuncSetAttribute(precompute_mma_kernel, cudaFuncAttributeMaxDynamicSharedMemorySize, SMEM_PRE);

    init_kernel<<<512, 256>>>();
    permute_kernel<<<2048, 256>>>(W, U, b, x);
    precompute_mma_kernel<<<dim3(FOURU_ / 64, (B_ * T_) / 64), 256, SMEM_PRE>>>();

    for (int t = 0; t < T_; t++) {
        step_mma_kernel<<<dim3(FOURU_ / 64, B_ / 64), 256, SMEM_STEP>>>(t);
        logits_kernel<<<dim3(NCL_ / LBN, B_ / LBM, 8), 256>>>(Wout, t);
        argmax_kernel<<<B_, 256>>>(bout, out, t);
    }
}

// round 17
// speedup vs baseline: 2.3047x; 1.0154x over previous
#include <cuda_runtime.h>
#include <cuda_bf16.h>
#include <mma.h>
#include <math.h>
#include <stdint.h>

using namespace nvcuda;

#define B_      256
#define T_      256
#define D_      512
#define UNITS_  1024
#define NCL_    512
#define FOURU_  4096

// ---------------- static device scratch (no allocs allowed) ----------------
__device__ float g_Zx[(size_t)T_ * B_ * FOURU_];     // [t][b][j'] = x_t @ Wx (permuted), NO bias
__device__ float g_Wwperm[(size_t)NCL_ * FOURU_];
__device__ float g_bperm[FOURU_];
__device__ __nv_bfloat16 g_Us[3][(size_t)FOURU_ * UNITS_];   // U splits, [n=j'][k] (K-major)
__device__ __nv_bfloat16 g_Wxs[3][(size_t)FOURU_ * D_];      // Wx splits, [n=j'][k] (K-major)
__device__ __nv_bfloat16 g_xs[3][(size_t)B_ * T_ * D_];      // x splits, [m=b*T+t][k]
__device__ __nv_bfloat16 g_hs[2][3][B_ * UNITS_];            // h splits ping-pong [b][k]
__device__ float g_h0[B_ * UNITS_];
__device__ float g_h1[B_ * UNITS_];
__device__ float g_c[B_ * UNITS_];
__device__ int   g_idx[B_];
__device__ float g_lpart[(size_t)8 * B_ * NCL_];     // logit partials

// ---------------- numerics helpers (bit-matching XLA) ----------------
__device__ __forceinline__ float hsig(float z) {
    float t = __fadd_rn(__fmul_rn(0.2f, z), 0.5f);
    return fminf(fmaxf(t, 0.0f), 1.0f);
}
__device__ __forceinline__ float tanh_xla(float x) {
    float ax = fabsf(x);
    if (ax < 0.0004f) return x;
    float xc = fminf(fmaxf(x, -9.0f), 9.0f);
    float x2 = __fmul_rn(xc, xc);
    float p = -2.76076847742355e-16f;
    p = fmaf(p, x2, 2.00018790482477e-13f);
    p = fmaf(p, x2, -8.60467152213735e-11f);
    p = fmaf(p, x2, 5.12229709037114e-08f);
    p = fmaf(p, x2, 1.48572235717979e-05f);
    p = fmaf(p, x2, 6.37261928875436e-04f);
    p = fmaf(p, x2, 4.89352455891786e-03f);
    float num = __fmul_rn(xc, p);
    float q = 1.19825839466702e-06f;
    q = fmaf(q, x2, 1.18534705686654e-04f);
    q = fmaf(q, x2, 2.26843463243900e-03f);
    q = fmaf(q, x2, 4.89352518554385e-03f);
    return __fdiv_rn(num, q);
}

__device__ __forceinline__ uint32_t smem_u32(const void* p) {
    uint32_t a;
    asm("{ .reg .u64 t; cvta.to.shared.u64 t, %1; cvt.u32.u64 %0, t; }" : "=r"(a) : "l"(p));
    return a;
}
__device__ __forceinline__ void cp_async16(uint32_t dst, const void* src) {
    asm volatile("cp.async.cg.shared.global [%0], [%1], 16;" :: "r"(dst), "l"(src));
}
__device__ __forceinline__ void cp_commit() {
    asm volatile("cp.async.commit_group;");
}
__device__ __forceinline__ void cp_wait1() {
    asm volatile("cp.async.wait_group 1;");
}
__device__ __forceinline__ void cp_wait0() {
    asm volatile("cp.async.wait_group 0;");
}

// ---------------- init ----------------
__global__ void init_kernel() {
    int stride = gridDim.x * blockDim.x;
    for (int i = blockIdx.x * blockDim.x + threadIdx.x; i < B_ * UNITS_; i += stride) {
        g_h0[i] = 0.0f;
        g_c[i] = 0.0f;
        g_hs[0][0][i] = __float2bfloat16(0.0f);
        g_hs[0][1][i] = __float2bfloat16(0.0f);
        g_hs[0][2][i] = __float2bfloat16(0.0f);
        if (i < B_) g_idx[i] = -1;
    }
}

// ---------------- permute weights + build all bf16 splits ----------------
__global__ void permute_kernel(const float* __restrict__ W,
                               const float* __restrict__ U,
                               const float* __restrict__ b,
                               const float* __restrict__ x) {
    int stride = gridDim.x * blockDim.x;
    int tid0 = blockIdx.x * blockDim.x + threadIdx.x;
    // Ww / bias, gate-interleaved columns j' = 4u + g
    for (int i = tid0; i < NCL_ * FOURU_; i += stride) {
        int k  = i >> 12;
        int jp = i & 4095;
        int src = ((jp & 3) << 10) + (jp >> 2);
        g_Wwperm[i] = W[((size_t)(k + D_) << 12) + src];
        if (k == 0) g_bperm[jp] = b[src];
    }
    // U transposed to [n=j'][k], split into 3 bf16 terms
    for (int i = tid0; i < FOURU_ * UNITS_; i += stride) {
        int jp = i >> 10;
        int k  = i & 1023;
        int src = ((jp & 3) << 10) + (jp >> 2);
        float v = U[((size_t)k << 12) + src];
        __nv_bfloat16 v1 = __float2bfloat16(v);
        float r1 = v - __bfloat162float(v1);
        __nv_bfloat16 v2 = __float2bfloat16(r1);
        float r2 = r1 - __bfloat162float(v2);
        g_Us[0][i] = v1;
        g_Us[1][i] = v2;
        g_Us[2][i] = __float2bfloat16(r2);
    }
    // Wx transposed to [n=j'][k], split into 3 bf16 terms
    for (int i = tid0; i < FOURU_ * D_; i += stride) {
        int jp = i >> 9;
        int k  = i & 511;
        int src = ((jp & 3) << 10) + (jp >> 2);
        float v = W[((size_t)k << 12) + src];
        __nv_bfloat16 v1 = __float2bfloat16(v);
        float r1 = v - __bfloat162float(v1);
        __nv_bfloat16 v2 = __float2bfloat16(r1);
        float r2 = r1 - __bfloat162float(v2);
        g_Wxs[0][i] = v1;
        g_Wxs[1][i] = v2;
        g_Wxs[2][i] = __float2bfloat16(r2);
    }
    // x split into 3 bf16 terms, [m][k] row-major (natural layout)
    for (size_t i = tid0; i < (size_t)B_ * T_ * D_; i += stride) {
        float v = x[i];
        __nv_bfloat16 v1 = __float2bfloat16(v);
        float r1 = v - __bfloat162float(v1);
        __nv_bfloat16 v2 = __float2bfloat16(r1);
        float r2 = r1 - __bfloat162float(v2);
        g_xs[0][i] = v1;
        g_xs[1][i] = v2;
        g_xs[2][i] = __float2bfloat16(r2);
    }
}

// ---------------- shared wmma GEMM config ----------------
// CTA tile M=64 x N=64, 8 warps as 2(m) x 4(n), warp tile 32x16.
// accA = a1*b1 pair only; accS = 5 small pairs; merged with one __fadd_rn.
// Accumulation chains BIT-IDENTICAL to R14/R15/R16 (passed rel_err = 0).
// NOTE: pair-index tables MUST be local const arrays (R13 spill lesson).
#define SKT     32
#define APAD    40
#define A_PLANE (64 * APAD)            // 2560 bf16
#define B_PLANE (64 * APAD)
#define ABUF    (3 * A_PLANE)
#define BBUF    (3 * B_PLANE)
#define BUFELEM (ABUF + BBUF)          // 15360 bf16 = 30720 B
#define STG_LD  68

// precompute: 3-buffer pipeline (R15, kept)
#define SMEM_PRE (3 * BUFELEM * 2)     // 92160 B

// step: 2-buffer pipeline + epilogue prefetch region
#define PRE_ZX   (2 * BUFELEM * 2)     // 61440: Zx tile 64x64 f32 (16384 B)
#define PRE_WW   (PRE_ZX + 16384)      // 77824: Ww gather 64x64 f32 (16384 B)
#define PRE_C    (PRE_WW + 16384)      // 94208: c slice 64x16 f32 (4096 B)
#define PRE_B    (PRE_C + 4096)        // 98304: bias slice 64 f32 (256 B)
#define SMEM_STEP (PRE_B + 256)        // 98560 B (2 CTAs/SM: 197120 <= 227 KB)

// ---------------- precompute: Zx = x @ Wxperm via wmma split-6 (R15 form) ----------------
__global__ void __launch_bounds__(256, 2) precompute_mma_kernel() {
    extern __shared__ char smem[];
    __nv_bfloat16* sb = (__nv_bfloat16*)smem;
    uint32_t sb_addr = smem_u32(smem);

    int tid = threadIdx.x;
    int wid = tid >> 5;
    int wm = wid & 1;
    int wn = wid >> 1;
    int n0 = blockIdx.x * 64;
    int m0 = blockIdx.y * 64;

    wmma::fragment<wmma::accumulator, 16, 16, 16, float> accA[2], accS[2];
#pragma unroll
    for (int i = 0; i < 2; i++) {
        wmma::fill_fragment(accA[i], 0.0f);
        wmma::fill_fragment(accS[i], 0.0f);
    }

    auto load_tile = [&](int kt, int buf) {
        uint32_t base = sb_addr + (uint32_t)buf * (BUFELEM * 2);
#pragma unroll
        for (int i = 0; i < 6; i++) {
            int idx = i * 256 + tid;
            if (idx < 768) {
                int s = idx >> 8;
                int rem = idx & 255;
                int row = rem >> 2, kc = rem & 3;
                uint32_t dst = base + (uint32_t)(s * A_PLANE + row * APAD + kc * 8) * 2;
                const void* src = &g_xs[s][(size_t)(m0 + row) * D_ + kt * SKT + kc * 8];
                cp_async16(dst, src);
            } else {
                int bidx = idx - 768;
                int s = bidx >> 8;
                int rem = bidx & 255;
                int n = rem >> 2, kc = rem & 3;
                uint32_t dst = base + (uint32_t)(ABUF + s * B_PLANE + n * APAD + kc * 8) * 2;
                const void* src = &g_Wxs[s][(size_t)(n0 + n) * D_ + kt * SKT + kc * 8];
                cp_async16(dst, src);
            }
        }
    };

    const int si[5] = {0, 1, 1, 0, 2};
    const int sj[5] = {1, 0, 1, 2, 0};

    const int NKT = D_ / SKT;           // 16
    load_tile(0, 0);
    cp_commit();
    load_tile(1, 1);
    cp_commit();

    int cbuf = 0, lbuf = 2;
    for (int kt = 0; kt < NKT; kt++) {
        if (kt + 1 < NKT) cp_wait1(); else cp_wait0();
        __syncthreads();
        if (kt + 2 < NKT) {
            load_tile(kt + 2, lbuf);
            cp_commit();
        }

        const __nv_bfloat16* abase = sb + (size_t)cbuf * BUFELEM;
        const __nv_bfloat16* bbase = abase + ABUF;

#pragma unroll
        for (int ksub = 0; ksub < 2; ksub++) {
            wmma::fragment<wmma::matrix_a, 16, 16, 16, __nv_bfloat16, wmma::row_major> af[3][2];
            wmma::fragment<wmma::matrix_b, 16, 16, 16, __nv_bfloat16, wmma::col_major> bf[3];
#pragma unroll
            for (int s = 0; s < 3; s++) {
#pragma unroll
                for (int im = 0; im < 2; im++)
                    wmma::load_matrix_sync(af[s][im],
                        abase + s * A_PLANE + (wm * 32 + im * 16) * APAD + ksub * 16, APAD);
                wmma::load_matrix_sync(bf[s],
                    bbase + s * B_PLANE + (wn * 16) * APAD + ksub * 16, APAD);
            }
#pragma unroll
            for (int im = 0; im < 2; im++)
                wmma::mma_sync(accA[im], af[0][im], bf[0], accA[im]);
#pragma unroll
            for (int p = 0; p < 5; p++)
#pragma unroll
                for (int im = 0; im < 2; im++)
                    wmma::mma_sync(accS[im], af[si[p]][im], bf[sj[p]], accS[im]);
        }
        cbuf = (cbuf + 1 == 3) ? 0 : cbuf + 1;
        lbuf = (lbuf + 1 == 3) ? 0 : lbuf + 1;
    }
    __syncthreads();

#pragma unroll
    for (int im = 0; im < 2; im++)
#pragma unroll
        for (int e = 0; e < accA[im].num_elements; e++)
            accA[im].x[e] = __fadd_rn(accA[im].x[e], accS[im].x[e]);

    float* stage = (float*)smem;
#pragma unroll
    for (int im = 0; im < 2; im++)
        wmma::store_matrix_sync(
            stage + (wm * 32 + im * 16) * STG_LD + wn * 16,
            accA[im], STG_LD, wmma::mem_row_major);
    __syncthreads();

#pragma unroll
    for (int it = 0; it < 4; it++) {
        int id = it * 256 + tid;
        int rrow = id >> 4;
        int qc = id & 15;
        int m = m0 + rrow;             // m = b*T + t
        int b = m >> 8;
        int t = m & 255;
        float4 v = *(const float4*)&stage[rrow * STG_LD + qc * 4];
        *(float4*)&g_Zx[((size_t)t * B_ + b) * FOURU_ + n0 + qc * 4] = v;
    }
}

// ---------------- step: wmma split-6 GEMM, 2-buf + epilogue smem prefetch ----------------
__global__ void __launch_bounds__(256, 2) step_mma_kernel(int t) {
    extern __shared__ char smem[];
    __nv_bfloat16* sb = (__nv_bfloat16*)smem;
    uint32_t sb_addr = smem_u32(smem);

    int tid = threadIdx.x;
    int wid = tid >> 5;
    int wm = wid & 1;
    int wn = wid >> 1;
    int n0 = blockIdx.x * 64;
    int m0 = blockIdx.y * 64;
    const __nv_bfloat16* hsrc = &g_hs[t & 1][0][0];
    const size_t HPLANE = (size_t)B_ * UNITS_;

    wmma::fragment<wmma::accumulator, 16, 16, 16, float> accA[2], accS[2];
#pragma unroll
    for (int i = 0; i < 2; i++) {
        wmma::fill_fragment(accA[i], 0.0f);
        wmma::fill_fragment(accS[i], 0.0f);
    }

    auto load_tile = [&](int kt, int buf) {
        uint32_t base = sb_addr + (uint32_t)buf * (BUFELEM * 2);
#pragma unroll
        for (int i = 0; i < 6; i++) {
            int idx = i * 256 + tid;
            if (idx < 768) {
                int s = idx >> 8;
                int rem = idx & 255;
                int row = rem >> 2, kc = rem & 3;
                uint32_t dst = base + (uint32_t)(s * A_PLANE + row * APAD + kc * 8) * 2;
                const void* src = hsrc + (size_t)s * HPLANE +
                                  (size_t)(m0 + row) * UNITS_ + kt * SKT + kc * 8;
                cp_async16(dst, src);
            } else {
                int bidx = idx - 768;
                int s = bidx >> 8;
                int rem = bidx & 255;
                int n = rem >> 2, kc = rem & 3;
                uint32_t dst = base + (uint32_t)(ABUF + s * B_PLANE + n * APAD + kc * 8) * 2;
                const void* src = &g_Us[s][(size_t)(n0 + n) * UNITS_ + kt * SKT + kc * 8];
                cp_async16(dst, src);
            }
        }
    };

    const int si[5] = {0, 1, 1, 0, 2};
    const int sj[5] = {1, 0, 1, 2, 0};

    // ---- epilogue prefetch: Zx tile, Ww gather, c slice, bias (joins group 0)
    {
#pragma unroll
        for (int i = 0; i < 4; i++) {              // Zx: 1024 chunks
            int ch = i * 256 + tid;
            int r = ch >> 4, c16 = ch & 15;
            cp_async16(sb_addr + PRE_ZX + r * 256 + c16 * 16,
                       &g_Zx[((size_t)t * B_ + m0 + r) * FOURU_ + n0 + c16 * 4]);
        }
#pragma unroll
        for (int i = 0; i < 4; i++) {              // Ww: 1024 chunks (guarded by idx)
            int ch = i * 256 + tid;
            int r = ch >> 4, c16 = ch & 15;
            int idx = g_idx[m0 + r];
            if (idx >= 0)
                cp_async16(sb_addr + PRE_WW + r * 256 + c16 * 16,
                           &g_Wwperm[(size_t)idx * FOURU_ + n0 + c16 * 4]);
        }
        {                                          // c: 256 chunks
            int r = tid >> 2, c16 = tid & 3;
            cp_async16(sb_addr + PRE_C + r * 64 + c16 * 16,
                       &g_c[(m0 + r) * UNITS_ + (n0 >> 2) + c16 * 4]);
        }
        if (tid < 16)                              // bias: 16 chunks
            cp_async16(sb_addr + PRE_B + tid * 16, &g_bperm[n0 + tid * 4]);
    }

    const int NKT = UNITS_ / SKT;       // 32
    load_tile(0, 0);
    cp_commit();                        // group 0 = prefetch + tile0

    for (int kt = 0; kt < NKT; kt++) {
        int buf = kt & 1;
        if (kt + 1 < NKT) {
            load_tile(kt + 1, buf ^ 1);
            cp_commit();
            cp_wait1();
        } else {
            cp_wait0();
        }
        __syncthreads();

        const __nv_bfloat16* abase = sb + (size_t)buf * BUFELEM;
        const __nv_bfloat16* bbase = abase + ABUF;

#pragma unroll
        for (int ksub = 0; ksub < 2; ksub++) {
            wmma::fragment<wmma::matrix_a, 16, 16, 16, __nv_bfloat16, wmma::row_major> af[3][2];
            wmma::fragment<wmma::matrix_b, 16, 16, 16, __nv_bfloat16, wmma::col_major> bf[3];
#pragma unroll
            for (int s = 0; s < 3; s++) {
#pragma unroll
                for (int im = 0; im < 2; im++)
                    wmma::load_matrix_sync(af[s][im],
                        abase + s * A_PLANE + (wm * 32 + im * 16) * APAD + ksub * 16, APAD);
                wmma::load_matrix_sync(bf[s],
                    bbase + s * B_PLANE + (wn * 16) * APAD + ksub * 16, APAD);
            }
            // main term -> accA (bit-identical chain to R14/R15/R16)
#pragma unroll
            for (int im = 0; im < 2; im++)
                wmma::mma_sync(accA[im], af[0][im], bf[0], accA[im]);
            // 5 small terms -> accS
#pragma unroll
            for (int p = 0; p < 5; p++)
#pragma unroll
                for (int im = 0; im < 2; im++)
                    wmma::mma_sync(accS[im], af[si[p]][im], bf[sj[p]], accS[im]);
        }
    }

#pragma unroll
    for (int im = 0; im < 2; im++)
#pragma unroll
        for (int e = 0; e < accA[im].num_elements; e++)
            accA[im].x[e] = __fadd_rn(accA[im].x[e], accS[im].x[e]);

    // stage area [0, 17408) lies in buffer 0; last compute used buffer 1
    // (NKT even), and every warp passed the kt=31 barrier -> buffer 0 free.
    float* stage = (float*)smem;
#pragma unroll
    for (int im = 0; im < 2; im++)
        wmma::store_matrix_sync(
            stage + (wm * 32 + im * 16) * STG_LD + wn * 16,
            accA[im], STG_LD, wmma::mem_row_major);
    __syncthreads();

    float* h_out = (t & 1) ? g_h0 : g_h1;
    int pnew = (t + 1) & 1;
#pragma unroll
    for (int it = 0; it < 4; it++) {
        int id = it * 256 + tid;
        int rrow = id >> 4;
        int qc = id & 15;
        int bat = m0 + rrow;
        int idx = g_idx[bat];
        int jb = n0 + qc * 4;

        float4 zx4 = *(const float4*)(smem + PRE_ZX + rrow * 256 + qc * 16);
        float ins[4] = {zx4.x, zx4.y, zx4.z, zx4.w};
        if (idx >= 0) {
            float4 ww = *(const float4*)(smem + PRE_WW + rrow * 256 + qc * 16);
            ins[0] = __fadd_rn(ins[0], ww.x);
            ins[1] = __fadd_rn(ins[1], ww.y);
            ins[2] = __fadd_rn(ins[2], ww.z);
            ins[3] = __fadd_rn(ins[3], ww.w);
        }
        float4 b4 = *(const float4*)(smem + PRE_B + qc * 16);
        float bv[4] = {b4.x, b4.y, b4.z, b4.w};
        float4 ac4 = *(const float4*)&stage[rrow * STG_LD + qc * 4];
        float av[4] = {ac4.x, ac4.y, ac4.z, ac4.w};
        float z[4];
#pragma unroll
        for (int g = 0; g < 4; g++)
            z[g] = __fadd_rn(__fadd_rn(ins[g], av[g]), bv[g]);

        int u = jb >> 2;
        float cold = *(const float*)(smem + PRE_C + rrow * 64 + qc * 4);
        float m1 = __fmul_rn(hsig(z[1]), cold);
        float m2 = __fmul_rn(hsig(z[0]), tanh_xla(z[2]));
        float cn = __fadd_rn(m1, m2);
        float hn = __fmul_rn(hsig(z[3]), tanh_xla(cn));
        g_c[bat * UNITS_ + u] = cn;
        h_out[bat * UNITS_ + u] = hn;

        __nv_bfloat16 h1 = __float2bfloat16(hn);
        float r1 = hn - __bfloat162float(h1);
        __nv_bfloat16 h2 = __float2bfloat16(r1);
        float r2 = r1 - __bfloat162float(h2);
        __nv_bfloat16 h3 = __float2bfloat16(r2);
        g_hs[pnew][0][bat * UNITS_ + u] = h1;
        g_hs[pnew][1][bat * UNITS_ + u] = h2;
        g_hs[pnew][2][bat * UNITS_ + u] = h3;
    }
}

// ---------------- logits partials: h_new @ Wout, 64x64 tiles, K split x8 ----------------
// Register-double-buffered: next iter's global loads issued before compute,
// ONE barrier per k-iter. FMA chain per thread is BIT-IDENTICAL to R16's
// (k0 ascending, kk 0..15, same fmaf order) -- only data staging changed.
#define BK 16
#define LBM 64
#define LBN 64
#define LASTRIDE (LBM + 4)

__global__ void __launch_bounds__(256) logits_kernel(const float* __restrict__ Wout, int t) {
    const float* __restrict__ h = (t & 1) ? g_h0 : g_h1;   // h_new written by step t

    __shared__ float As[2][BK][LASTRIDE];
    __shared__ float Bs[2][BK][LBN];
    int tid = threadIdx.x;
    int tx = tid & 15, ty = tid >> 4;
    int m0 = blockIdx.y * LBM;
    int n0 = blockIdx.x * LBN;
    int kc = blockIdx.z;
    int kbeg = kc * 128;

    int arow = tid >> 2, ac4 = tid & 3;    // A load coords
    int brow = tid >> 4, bc4 = tid & 15;   // B load coords

    float acc[4][4];
#pragma unroll
    for (int i = 0; i < 4; i++)
#pragma unroll
        for (int j = 0; j < 4; j++) acc[i][j] = 0.0f;

    // preload iter 0 into regs, stage into buffer 0
    float4 va = *(const float4*)&h[(size_t)(m0 + arow) * UNITS_ + kbeg + ac4 * 4];
    float4 vb = *(const float4*)&Wout[(size_t)(kbeg + brow) * NCL_ + n0 + bc4 * 4];
    As[0][ac4 * 4 + 0][arow] = va.x;
    As[0][ac4 * 4 + 1][arow] = va.y;
    As[0][ac4 * 4 + 2][arow] = va.z;
    As[0][ac4 * 4 + 3][arow] = va.w;
    *(float4*)&Bs[0][brow][bc4 * 4] = vb;
    __syncthreads();

#pragma unroll
    for (int it = 0; it < 8; it++) {
        // issue next iter's global loads early (latency overlapped with compute)
        if (it + 1 < 8) {
            int k0n = kbeg + (it + 1) * BK;
            va = *(const float4*)&h[(size_t)(m0 + arow) * UNITS_ + k0n + ac4 * 4];
            vb = *(const float4*)&Wout[(size_t)(k0n + brow) * NCL_ + n0 + bc4 * 4];
        }

        int cb = it & 1;
#pragma unroll
        for (int kk = 0; kk < BK; kk++) {
            float4 a4 = *(const float4*)&As[cb][kk][ty * 4];
            float4 b4 = *(const float4*)&Bs[cb][kk][tx * 4];
            float a[4] = {a4.x, a4.y, a4.z, a4.w};
            float bb[4] = {b4.x, b4.y, b4.z, b4.w};
#pragma unroll
            for (int i = 0; i < 4; i++)
#pragma unroll
                for (int j = 0; j < 4; j++) acc[i][j] = fmaf(a[i], bb[j], acc[i][j]);
        }

        if (it + 1 < 8) {
            int nb = cb ^ 1;
            // safe: buffer nb was last READ at iter it-1, which completed
            // before the barrier everyone passed to enter iter it.
            As[nb][ac4 * 4 + 0][arow] = va.x;
            As[nb][ac4 * 4 + 1][arow] = va.y;
            As[nb][ac4 * 4 + 2][arow] = va.z;
            As[nb][ac4 * 4 + 3][arow] = va.w;
            *(float4*)&Bs[nb][brow][bc4 * 4] = vb;
            __syncthreads();
        }
    }

#pragma unroll
    for (int i = 0; i < 4; i++) {
        int m = m0 + ty * 4 + i;
        float* dst = &g_lpart[((size_t)kc * B_ + m) * NCL_ + n0 + tx * 4];
        *(float4*)dst = make_float4(acc[i][0], acc[i][1], acc[i][2], acc[i][3]);
    }
}

// ---------------- reduce partials + bias, argmax (tie -> lowest index) ----------------
__global__ void __launch_bounds__(256) argmax_kernel(const float* __restrict__ bout,
                                                     float* __restrict__ out, int t) {
    int b = blockIdx.x;
    int tid = threadIdx.x;
    unsigned long long best = 0ull;
    for (int n = tid; n < NCL_; n += 256) {
        float l = 0.0f;
#pragma unroll
        for (int kc = 0; kc < 8; kc++)
            l = __fadd_rn(l, g_lpart[((size_t)kc * B_ + b) * NCL_ + n]);
        l = __fadd_rn(l, bout[n]);
        unsigned u = __float_as_uint(l);
        u = (u & 0x80000000u) ? ~u : (u | 0x80000000u);
        unsigned long long key = ((unsigned long long)u << 32) | (unsigned)(NCL_ - 1 - n);
        best = best > key ? best : key;
    }
    __shared__ unsigned long long red[256];
    red[tid] = best;
    __syncthreads();
    for (int s = 128; s > 0; s >>= 1) {
        if (tid < s) red[tid] = red[tid] > red[tid + s] ? red[tid] : red[tid + s];
        __syncthreads();
    }
    if (tid == 0) {
        int idx = (NCL_ - 1) - (int)(red[0] & 0xffffffffu);
        g_idx[b] = idx;
        out[(size_t)b * T_ + t] = (float)idx;   // output dtype: float32
    }
}

// ---------------- launch (3 + 256*3 = 771 graph nodes, proven infra-safe) ----------------
extern "C" void kernel_launch(void* const* d_in, const int* in_sizes, int n_in,
                              void* d_out, int out_size) {
    (void)out_size;
    const float *x = 0, *W = 0, *U = 0, *b = 0, *Wout = 0, *bout = 0;
    const float* big[2] = {0, 0};
    int nbig = 0;
    for (int i = 0; i < n_in; i++) {
        switch (in_sizes[i]) {
            case 33554432: x    = (const float*)d_in[i]; break;  // 256*256*512
            case 524288:   Wout = (const float*)d_in[i]; break;  // 1024*512
            case 4096:     b    = (const float*)d_in[i]; break;
            case 512:      bout = (const float*)d_in[i]; break;
            case 4194304:  if (nbig < 2) big[nbig++] = (const float*)d_in[i]; break;
            default: break;
        }
    }
    W = big[0];
    U = big[1];
    float* out = (float*)d_out;

    cudaFuncSetAttribute(step_mma_kernel, cudaFuncAttributeMaxDynamicSharedMemorySize, SMEM_STEP);
    cudaFuncSetAttribute(precompute_mma_kernel, cudaFuncAttributeMaxDynamicSharedMemorySize, SMEM_PRE);

    init_kernel<<<512, 256>>>();
    permute_kernel<<<2048, 256>>>(W, U, b, x);
    precompute_mma_kernel<<<dim3(FOURU_ / 64, (B_ * T_) / 64), 256, SMEM_PRE>>>();

    for (int t = 0; t < T_; t++) {
        step_mma_kernel<<<dim3(FOURU_ / 64, B_ / 64), 256, SMEM_STEP>>>(t);
        logits_kernel<<<dim3(NCL_ / LBN, B_ / LBM, 8), 256>>>(Wout, t);
        argmax_kernel<<<B_, 256>>>(bout, out, t);
    }
}